// round 1
// baseline (speedup 1.0000x reference)
#include <cuda_runtime.h>
#include <math.h>

// Problem constants
#define BB      4
#define TT      4096
#define DIMV    1024
#define MFEAT   512
#define RROWS   (BB * TT)        // 16384 rows per tensor
#define NROWS   (2 * RROWS)      // Q rows then masked-K rows
#define RSQRTM  0.04419417382415922f   // 1/sqrt(512)
#define EPSV    1e-8f

// ---------------- device scratch (static, allocation-free) ----------------
__device__ float g_qp[RROWS * MFEAT];       // 32 MB
__device__ float g_kp[RROWS * MFEAT];       // 32 MB
__device__ float g_xd[NROWS];               // 0.5*||x||^2 per row (Q rows, then masked-K rows)
__device__ float g_ksum[BB * MFEAT];
__device__ float g_D[BB * TT];
__device__ float g_kptv[BB * DIMV * MFEAT]; // 8 MB
__device__ int   g_flag;                    // 1 iff any feature value is nonzero

// ---------------- kernel 0: reset flag ----------------
__global__ void reset_kernel() {
    if (threadIdx.x == 0) g_flag = 0;
}

// ---------------- kernel 1: row squared-norms (xd) ----------------
__global__ void xd_kernel(const float* __restrict__ Q,
                          const float* __restrict__ Kin,
                          const float* __restrict__ mask) {
    int row = blockIdx.x;               // 0 .. NROWS-1
    const float* p;
    float s;
    if (row < RROWS) { p = Q + (size_t)row * DIMV; s = 1.0f; }
    else             { int kr = row - RROWS; p = Kin + (size_t)kr * DIMV; s = mask[kr]; }
    int tid = threadIdx.x;              // 128 threads
    float sum = 0.0f;
    const float4* p4 = reinterpret_cast<const float4*>(p);
    #pragma unroll
    for (int i = tid; i < DIMV / 4; i += 128) {
        float4 v = p4[i];
        sum += v.x * v.x + v.y * v.y + v.z * v.z + v.w * v.w;
    }
    #pragma unroll
    for (int o = 16; o; o >>= 1) sum += __shfl_xor_sync(0xFFFFFFFFu, sum, o);
    __shared__ float ws[4];
    if ((tid & 31) == 0) ws[tid >> 5] = sum;
    __syncthreads();
    if (tid == 0)
        g_xd[row] = 0.5f * (ws[0] + ws[1] + ws[2] + ws[3]) * s * s;
}

// ---------------- kernel 2: feature GEMM + exp epilogue ----------------
// C[r, m] = exp( X[r,:] . w[m,:] - xd[r] ) / sqrt(M)
// X = [Q rows ; mask*K rows], stored to g_qp / g_kp. Sets g_flag if any nonzero.
// Tiling: BM=128, BN=64, BK=16, 256 threads, thread tile 8x4, double-buffered smem,
// XOR-swizzled shared stores (conflict-free STS/LDS).
#define BMt 128
#define BNt 64
#define BKt 16
__global__ void __launch_bounds__(256)
feat_gemm(const float* __restrict__ Q, const float* __restrict__ Kin,
          const float* __restrict__ mask, const float* __restrict__ w) {
    __shared__ float As[2][BKt][BMt];
    __shared__ float Bs[2][BKt][BNt];

    const int tid = threadIdx.x;
    const int bm = blockIdx.y * BMt;     // row base
    const int bn = blockIdx.x * BNt;     // feature base
    const int tx = tid & 15;             // 0..15 -> 4 n each
    const int ty = tid >> 4;             // 0..15 -> 8 rows each

    // loaders
    const int lrow = tid >> 2;           // 0..63
    const int lk   = (tid & 3) * 4;      // k offset within tile (float4)
    const int qsw  = (tid & 3);          // swizzle group = (k>>2)&3 for all 4 stored k's

    const float* aptr[2];
    float ascale[2];
    #pragma unroll
    for (int i = 0; i < 2; i++) {
        int gr = bm + lrow + 64 * i;
        if (gr < RROWS) { aptr[i] = Q + (size_t)gr * DIMV; ascale[i] = 1.0f; }
        else { int kr = gr - RROWS; aptr[i] = Kin + (size_t)kr * DIMV; ascale[i] = mask[kr]; }
    }
    const float* bptr = w + (size_t)(bn + lrow) * DIMV;

    float4 aReg[2], bReg;
    float acc[8][4];
    #pragma unroll
    for (int i = 0; i < 8; i++)
        #pragma unroll
        for (int j = 0; j < 4; j++) acc[i][j] = 0.0f;

    // prologue load + store tile 0
    #pragma unroll
    for (int i = 0; i < 2; i++) {
        float4 v = *reinterpret_cast<const float4*>(aptr[i] + lk);
        v.x *= ascale[i]; v.y *= ascale[i]; v.z *= ascale[i]; v.w *= ascale[i];
        aReg[i] = v;
    }
    bReg = *reinterpret_cast<const float4*>(bptr + lk);

    {
        #pragma unroll
        for (int i = 0; i < 2; i++) {
            int row = lrow + 64 * i;
            int col = row ^ (qsw * 8);
            As[0][lk + 0][col] = aReg[i].x;
            As[0][lk + 1][col] = aReg[i].y;
            As[0][lk + 2][col] = aReg[i].z;
            As[0][lk + 3][col] = aReg[i].w;
        }
        int col = lrow ^ (qsw * 8);
        Bs[0][lk + 0][col] = bReg.x;
        Bs[0][lk + 1][col] = bReg.y;
        Bs[0][lk + 2][col] = bReg.z;
        Bs[0][lk + 3][col] = bReg.w;
    }
    __syncthreads();

    int buf = 0;
    const int NKT = DIMV / BKt;          // 64
    for (int kt = 0; kt < NKT; kt++) {
        if (kt < NKT - 1) {
            int k0 = (kt + 1) * BKt;
            #pragma unroll
            for (int i = 0; i < 2; i++) {
                float4 v = *reinterpret_cast<const float4*>(aptr[i] + k0 + lk);
                v.x *= ascale[i]; v.y *= ascale[i]; v.z *= ascale[i]; v.w *= ascale[i];
                aReg[i] = v;
            }
            bReg = *reinterpret_cast<const float4*>(bptr + k0 + lk);
        }
        #pragma unroll
        for (int k = 0; k < BKt; k++) {
            int qr = k >> 2;
            int cA = (ty ^ qr) * 8;
            float4 a0 = *reinterpret_cast<const float4*>(&As[buf][k][cA]);
            float4 a1 = *reinterpret_cast<const float4*>(&As[buf][k][cA + 4]);
            int cB = (tx * 4) ^ (qr * 8);
            float4 b0 = *reinterpret_cast<const float4*>(&Bs[buf][k][cB]);
            float av[8] = {a0.x, a0.y, a0.z, a0.w, a1.x, a1.y, a1.z, a1.w};
            float bv[4] = {b0.x, b0.y, b0.z, b0.w};
            #pragma unroll
            for (int i = 0; i < 8; i++)
                #pragma unroll
                for (int j = 0; j < 4; j++)
                    acc[i][j] = fmaf(av[i], bv[j], acc[i][j]);
        }
        if (kt < NKT - 1) {
            int nb = buf ^ 1;
            #pragma unroll
            for (int i = 0; i < 2; i++) {
                int row = lrow + 64 * i;
                int col = row ^ (qsw * 8);
                As[nb][lk + 0][col] = aReg[i].x;
                As[nb][lk + 1][col] = aReg[i].y;
                As[nb][lk + 2][col] = aReg[i].z;
                As[nb][lk + 3][col] = aReg[i].w;
            }
            int col = lrow ^ (qsw * 8);
            Bs[nb][lk + 0][col] = bReg.x;
            Bs[nb][lk + 1][col] = bReg.y;
            Bs[nb][lk + 2][col] = bReg.z;
            Bs[nb][lk + 3][col] = bReg.w;
            __syncthreads();
            buf = nb;
        }
    }

    // epilogue: exp + store + nonzero flag
    bool nz = false;
    #pragma unroll
    for (int i = 0; i < 8; i++) {
        int r = bm + ty * 8 + i;
        float xd = g_xd[r];
        float4 o;
        o.x = expf(acc[i][0] - xd) * RSQRTM;
        o.y = expf(acc[i][1] - xd) * RSQRTM;
        o.z = expf(acc[i][2] - xd) * RSQRTM;
        o.w = expf(acc[i][3] - xd) * RSQRTM;
        nz = nz || (o.x != 0.0f) || (o.y != 0.0f) || (o.z != 0.0f) || (o.w != 0.0f);
        float* out = (r < RROWS) ? (g_qp + (size_t)r * MFEAT)
                                 : (g_kp + (size_t)(r - RROWS) * MFEAT);
        *reinterpret_cast<float4*>(out + bn + tx * 4) = o;
    }
    if (nz) atomicOr(&g_flag, 1);
}

// ---------------- gated tail (executes real math only if g_flag != 0) ------

// ksum[b, m] = sum_t kp[b, t, m]
__global__ void ksum_kernel() {
    if (g_flag == 0) return;
    int b = blockIdx.z;
    int m = blockIdx.x * 256 + threadIdx.x;   // grid.x = 2
    float acc = 0.0f;
    for (int t = 0; t < TT; t++)
        acc += g_kp[((size_t)b * TT + t) * MFEAT + m];
    g_ksum[b * MFEAT + m] = acc;
}

// D[b, t] = sum_m qp[b, t, m] * ksum[b, m]
__global__ void dvec_kernel() {
    if (g_flag == 0) return;
    int bt = blockIdx.x;                      // 0..BB*TT-1
    int b = bt / TT;
    int tid = threadIdx.x;                    // 128
    float acc = 0.0f;
    #pragma unroll
    for (int m = tid; m < MFEAT; m += 128)
        acc += g_qp[(size_t)bt * MFEAT + m] * g_ksum[b * MFEAT + m];
    #pragma unroll
    for (int o = 16; o; o >>= 1) acc += __shfl_xor_sync(0xFFFFFFFFu, acc, o);
    __shared__ float ws[4];
    if ((tid & 31) == 0) ws[tid >> 5] = acc;
    __syncthreads();
    if (tid == 0) g_D[bt] = ws[0] + ws[1] + ws[2] + ws[3];
}

// kptv[b, n, m] = sum_t (V[b,t,n]*mask[b,t]) * kp[b,t,m]
__global__ void kptv_kernel(const float* __restrict__ V,
                            const float* __restrict__ mask) {
    if (g_flag == 0) return;
    __shared__ float Vs[16][17], Ks[16][17];
    int b = blockIdx.z;
    int n0 = blockIdx.y * 16, m0 = blockIdx.x * 16;
    int tx = threadIdx.x, ty = threadIdx.y;
    float acc = 0.0f;
    for (int t0 = 0; t0 < TT; t0 += 16) {
        int t = t0 + ty;
        Vs[ty][tx] = V[((size_t)b * TT + t) * DIMV + n0 + tx] * mask[b * TT + t];
        Ks[ty][tx] = g_kp[((size_t)b * TT + t) * MFEAT + m0 + tx];
        __syncthreads();
        #pragma unroll
        for (int kk = 0; kk < 16; kk++)
            acc = fmaf(Vs[kk][ty], Ks[kk][tx], acc);
        __syncthreads();
    }
    g_kptv[((size_t)b * DIMV + n0 + ty) * MFEAT + m0 + tx] = acc;
}

// y[b,t,n] = (sum_m qp[b,t,m]*kptv[b,n,m]) / (D+eps)^2
__global__ void y_full_kernel(float* __restrict__ out) {
    if (g_flag == 0) return;
    __shared__ float Qs[16][17], Ps[16][17];
    int b = blockIdx.z;
    int t0 = blockIdx.y * 16, n0 = blockIdx.x * 16;
    int tx = threadIdx.x, ty = threadIdx.y;
    float acc = 0.0f;
    for (int m0 = 0; m0 < MFEAT; m0 += 16) {
        Qs[ty][tx] = g_qp[((size_t)b * TT + t0 + ty) * MFEAT + m0 + tx];
        Ps[ty][tx] = g_kptv[((size_t)b * DIMV + n0 + ty) * MFEAT + m0 + tx];
        __syncthreads();
        #pragma unroll
        for (int kk = 0; kk < 16; kk++)
            acc = fmaf(Qs[ty][kk], Ps[tx][kk], acc);
        __syncthreads();
    }
    int t = t0 + ty;
    float inv = 1.0f / (g_D[b * TT + t] + EPSV);
    out[((size_t)b * TT + t) * DIMV + n0 + tx] = acc * inv * inv;
}

// zero writer (the expected fast path)
__global__ void y_zero_kernel(float* __restrict__ out) {
    if (g_flag != 0) return;
    size_t idx = (size_t)blockIdx.x * blockDim.x + threadIdx.x;
    reinterpret_cast<float4*>(out)[idx] = make_float4(0.f, 0.f, 0.f, 0.f);
}

// ---------------- launch ----------------
extern "C" void kernel_launch(void* const* d_in, const int* in_sizes, int n_in,
                              void* d_out, int out_size) {
    const float* Q    = (const float*)d_in[0];
    const float* K    = (const float*)d_in[1];
    const float* V    = (const float*)d_in[2];
    const float* mask = (const float*)d_in[3];
    const float* w    = (const float*)d_in[4];
    float* out = (float*)d_out;
    (void)in_sizes; (void)n_in; (void)out_size;

    reset_kernel<<<1, 32>>>();
    xd_kernel<<<NROWS, 128>>>(Q, K, mask);
    feat_gemm<<<dim3(MFEAT / BNt, NROWS / BMt), 256>>>(Q, K, mask, w);
    ksum_kernel<<<dim3(2, 1, BB), 256>>>();
    dvec_kernel<<<BB * TT, 128>>>();
    kptv_kernel<<<dim3(MFEAT / 16, DIMV / 16, BB), dim3(16, 16)>>>(V, mask);
    y_full_kernel<<<dim3(DIMV / 16, TT / 16, BB), dim3(16, 16)>>>(out);
    y_zero_kernel<<<(RROWS * DIMV) / 4 / 256, 256>>>(out);
}

// round 2
// speedup vs baseline: 2.6652x; 2.6652x over previous
#include <cuda_runtime.h>
#include <cuda_bf16.h>
#include <math.h>
#include <stdint.h>

// Problem constants
#define BB      4
#define TT      4096
#define DIMV    1024
#define MFEAT   512
#define RROWS   (BB * TT)        // 16384 rows per tensor
#define NROWS   (2 * RROWS)      // Q rows then masked-K rows
#define RSQRTM  0.04419417382415922f   // 1/sqrt(512)
#define EPSV    1e-8f

// ---------------- device scratch (static, allocation-free) ----------------
__device__ float g_qp[RROWS * MFEAT];       // 32 MB (fallback only)
__device__ float g_kp[RROWS * MFEAT];       // 32 MB (fallback only)
__device__ float g_xd[NROWS];               // 0.5*||x||^2 per row
__device__ float g_ksum[BB * MFEAT];
__device__ float g_D[BB * TT];
__device__ float g_kptv[BB * DIMV * MFEAT]; // 8 MB
__device__ int   g_flag;                    // 1 => certificate FAILED -> full fp32 path
__device__ int   g_wmaxsq_bits;             // max ||w_m||^2 as float bits (positive floats)

// ---------------- helpers ----------------
__device__ __forceinline__ uint32_t cvta_s(const void* p) {
    return (uint32_t)__cvta_generic_to_shared(p);
}

__device__ __forceinline__ void st_bf16x4(void* p, float4 v) {
    __nv_bfloat162 lo = __floats2bfloat162_rn(v.x, v.y);
    __nv_bfloat162 hi = __floats2bfloat162_rn(v.z, v.w);
    uint2 u;
    u.x = *reinterpret_cast<unsigned*>(&lo);
    u.y = *reinterpret_cast<unsigned*>(&hi);
    *reinterpret_cast<uint2*>(p) = u;
}

__device__ __forceinline__ void ldmx4(uint32_t* r, uint32_t addr) {
    asm volatile("ldmatrix.sync.aligned.m8n8.x4.shared.b16 {%0,%1,%2,%3}, [%4];"
                 : "=r"(r[0]), "=r"(r[1]), "=r"(r[2]), "=r"(r[3]) : "r"(addr));
}

__device__ __forceinline__ void mma_bf16(float* c, const uint32_t* a, uint32_t b0, uint32_t b1) {
    asm volatile(
        "mma.sync.aligned.m16n8k16.row.col.f32.bf16.bf16.f32 "
        "{%0,%1,%2,%3},{%4,%5,%6,%7},{%8,%9},{%0,%1,%2,%3};"
        : "+f"(c[0]), "+f"(c[1]), "+f"(c[2]), "+f"(c[3])
        : "r"(a[0]), "r"(a[1]), "r"(a[2]), "r"(a[3]), "r"(b0), "r"(b1));
}

// swizzled byte offset within a 64B-per-row tile: chunk = 16B unit index (0..3)
__device__ __forceinline__ int swz(int r, int chunk) {
    return r * 64 + ((chunk ^ ((r >> 1) & 3)) << 4);
}

// ---------------- kernel 0: reset flags ----------------
__global__ void reset_kernel() {
    if (threadIdx.x == 0) { g_flag = 0; g_wmaxsq_bits = 0; }
}

// ---------------- kernel 1: row squared-norms (xd) ----------------
__global__ void xd_kernel(const float* __restrict__ Q,
                          const float* __restrict__ Kin,
                          const float* __restrict__ mask) {
    int row = blockIdx.x;               // 0 .. NROWS-1
    const float* p;
    float s;
    if (row < RROWS) { p = Q + (size_t)row * DIMV; s = 1.0f; }
    else             { int kr = row - RROWS; p = Kin + (size_t)kr * DIMV; s = mask[kr]; }
    int tid = threadIdx.x;              // 128 threads
    float sum = 0.0f;
    const float4* p4 = reinterpret_cast<const float4*>(p);
    #pragma unroll
    for (int i = tid; i < DIMV / 4; i += 128) {
        float4 v = p4[i];
        sum += v.x * v.x + v.y * v.y + v.z * v.z + v.w * v.w;
    }
    #pragma unroll
    for (int o = 16; o; o >>= 1) sum += __shfl_xor_sync(0xFFFFFFFFu, sum, o);
    __shared__ float ws[4];
    if ((tid & 31) == 0) ws[tid >> 5] = sum;
    __syncthreads();
    if (tid == 0)
        g_xd[row] = 0.5f * (ws[0] + ws[1] + ws[2] + ws[3]) * s * s;
}

// ---------------- kernel 1b: max ||w_m||^2 ----------------
__global__ void wmax_kernel(const float* __restrict__ w) {
    int row = blockIdx.x;               // 0..511
    int tid = threadIdx.x;              // 128
    const float4* p4 = reinterpret_cast<const float4*>(w + (size_t)row * DIMV);
    float sum = 0.0f;
    #pragma unroll
    for (int i = tid; i < DIMV / 4; i += 128) {
        float4 v = p4[i];
        sum += v.x * v.x + v.y * v.y + v.z * v.z + v.w * v.w;
    }
    #pragma unroll
    for (int o = 16; o; o >>= 1) sum += __shfl_xor_sync(0xFFFFFFFFu, sum, o);
    __shared__ float ws[4];
    if ((tid & 31) == 0) ws[tid >> 5] = sum;
    __syncthreads();
    if (tid == 0) {
        float tot = ws[0] + ws[1] + ws[2] + ws[3];
        atomicMax(&g_wmaxsq_bits, __float_as_int(tot));
    }
}

// ---------------- kernel 2: bf16 tensor-core certificate GEMM ----------------
// Computes C = X * w^T in bf16 (X = [Q ; mask*K], 32768 x 1024; w 512 x 1024),
// NO stores of C. Flags g_flag=1 unless every element satisfies c <= xd - 122
// (which rigorously implies the exact fp32 feature exp(wtx - xd) == 0.0f and no
// overflow/NaN anywhere), given the guards ||x||^2<=14000 and max||w||^2<=1250.
#define CM 128
#define CN 64
__global__ void __launch_bounds__(256)
cert_gemm(const float* __restrict__ Q, const float* __restrict__ Kin,
          const float* __restrict__ mask, const float* __restrict__ w) {
    __shared__ __align__(16) unsigned char As[2][CM * 64];  // 2 x 8KB
    __shared__ __align__(16) unsigned char Bs[2][CN * 64];  // 2 x 4KB

    const int tid  = threadIdx.x;
    const int lane = tid & 31;
    const int warp = tid >> 5;
    const int wm = warp >> 1;          // 0..3  -> 32 rows each
    const int wn = warp & 1;           // 0..1  -> 32 cols each
    const int blockRow = blockIdx.y * CM;
    const int bn = blockIdx.x * CN;

    // ---- global loader mapping: 32 rows/pass, 8 threads per row ----
    const int lr = tid >> 3;           // 0..31
    const int kf = (tid & 7) * 4;      // float offset within 32-wide k tile

    const float* aptr[4]; float ascale[4];
    #pragma unroll
    for (int p = 0; p < 4; p++) {
        int gr = blockRow + p * 32 + lr;
        if (gr < RROWS) { aptr[p] = Q + (size_t)gr * DIMV; ascale[p] = 1.0f; }
        else { int kr = gr - RROWS; aptr[p] = Kin + (size_t)kr * DIMV; ascale[p] = mask[kr]; }
    }
    const float* bptr[2];
    #pragma unroll
    for (int p = 0; p < 2; p++)
        bptr[p] = w + (size_t)(bn + p * 32 + lr) * DIMV;

    // smem store byte offsets (swizzled)
    int aoff[4], boff[2];
    {
        int chunk = kf >> 3, sub = (kf >> 2) & 1;
        #pragma unroll
        for (int p = 0; p < 4; p++) aoff[p] = swz(p * 32 + lr, chunk) + sub * 8;
        #pragma unroll
        for (int p = 0; p < 2; p++) boff[p] = swz(p * 32 + lr, chunk) + sub * 8;
    }

    // ldmatrix byte offsets
    int lA[2][2], lB[2][2];
    #pragma unroll
    for (int i = 0; i < 2; i++)
        #pragma unroll
        for (int s = 0; s < 2; s++) {
            int rl = wm * 32 + i * 16 + (lane & 15);
            int cl = s * 2 + (lane >> 4);
            lA[i][s] = swz(rl, cl);
            int n  = wn * 32 + i * 16 + (lane & 7) + ((lane >> 4) << 3);
            int c2 = s * 2 + ((lane >> 3) & 1);
            lB[i][s] = swz(n, c2);
        }

    float acc[2][4][4];
    #pragma unroll
    for (int i = 0; i < 2; i++)
        #pragma unroll
        for (int j = 0; j < 4; j++)
            #pragma unroll
            for (int e = 0; e < 4; e++) acc[i][j][e] = 0.0f;

    const uint32_t sA = cvta_s(As);
    const uint32_t sB = cvta_s(Bs);

    float4 av[4], bv[2];
    // prologue: k-tile 0
    #pragma unroll
    for (int p = 0; p < 4; p++) {
        float4 v = *reinterpret_cast<const float4*>(aptr[p] + kf);
        v.x *= ascale[p]; v.y *= ascale[p]; v.z *= ascale[p]; v.w *= ascale[p];
        av[p] = v;
    }
    #pragma unroll
    for (int p = 0; p < 2; p++)
        bv[p] = *reinterpret_cast<const float4*>(bptr[p] + kf);
    #pragma unroll
    for (int p = 0; p < 4; p++) st_bf16x4(&As[0][aoff[p]], av[p]);
    #pragma unroll
    for (int p = 0; p < 2; p++) st_bf16x4(&Bs[0][boff[p]], bv[p]);
    __syncthreads();

    int buf = 0;
    const int NKT = DIMV / 32;         // 32 k-tiles
    for (int kt = 0; kt < NKT; kt++) {
        if (kt < NKT - 1) {
            int k0 = (kt + 1) * 32 + kf;
            #pragma unroll
            for (int p = 0; p < 4; p++) {
                float4 v = *reinterpret_cast<const float4*>(aptr[p] + k0);
                v.x *= ascale[p]; v.y *= ascale[p]; v.z *= ascale[p]; v.w *= ascale[p];
                av[p] = v;
            }
            #pragma unroll
            for (int p = 0; p < 2; p++)
                bv[p] = *reinterpret_cast<const float4*>(bptr[p] + k0);
        }
        uint32_t baseA = sA + buf * (CM * 64);
        uint32_t baseB = sB + buf * (CN * 64);
        #pragma unroll
        for (int s = 0; s < 2; s++) {
            uint32_t a0[4], a1[4], b0[4], b1[4];
            ldmx4(a0, baseA + lA[0][s]);
            ldmx4(a1, baseA + lA[1][s]);
            ldmx4(b0, baseB + lB[0][s]);
            ldmx4(b1, baseB + lB[1][s]);
            mma_bf16(acc[0][0], a0, b0[0], b0[1]);
            mma_bf16(acc[0][1], a0, b0[2], b0[3]);
            mma_bf16(acc[0][2], a0, b1[0], b1[1]);
            mma_bf16(acc[0][3], a0, b1[2], b1[3]);
            mma_bf16(acc[1][0], a1, b0[0], b0[1]);
            mma_bf16(acc[1][1], a1, b0[2], b0[3]);
            mma_bf16(acc[1][2], a1, b1[0], b1[1]);
            mma_bf16(acc[1][3], a1, b1[2], b1[3]);
        }
        if (kt < NKT - 1) {
            int nb = buf ^ 1;
            #pragma unroll
            for (int p = 0; p < 4; p++) st_bf16x4(&As[nb][aoff[p]], av[p]);
            #pragma unroll
            for (int p = 0; p < 2; p++) st_bf16x4(&Bs[nb][boff[p]], bv[p]);
            __syncthreads();
            buf = nb;
        }
    }

    // ---- certificate epilogue: no stores, just a flag ----
    bool bad = false;
    float wmaxsq = __int_as_float(g_wmaxsq_bits);
    if (!(wmaxsq <= 1250.0f)) bad = true;    // also catches NaN
    #pragma unroll
    for (int mi = 0; mi < 2; mi++) {
        int r0 = blockRow + wm * 32 + mi * 16 + (lane >> 2);
        float xd0 = g_xd[r0];
        float xd1 = g_xd[r0 + 8];
        if (!(xd0 <= 14000.0f) || !(xd1 <= 14000.0f)) bad = true;
        float t0 = xd0 - 122.0f;
        float t1 = xd1 - 122.0f;
        #pragma unroll
        for (int nj = 0; nj < 4; nj++) {
            if (!(acc[mi][nj][0] <= t0)) bad = true;
            if (!(acc[mi][nj][1] <= t0)) bad = true;
            if (!(acc[mi][nj][2] <= t1)) bad = true;
            if (!(acc[mi][nj][3] <= t1)) bad = true;
        }
    }
    if (__syncthreads_or(bad ? 1 : 0)) {
        if (tid == 0) atomicOr(&g_flag, 1);
    }
}

// ================= gated fallback: exact fp32 pipeline (runs iff g_flag) =====

#define BMt 128
#define BNt 64
#define BKt 16
__global__ void __launch_bounds__(256)
feat_gemm(const float* __restrict__ Q, const float* __restrict__ Kin,
          const float* __restrict__ mask, const float* __restrict__ w) {
    if (g_flag == 0) return;
    __shared__ float As[2][BKt][BMt];
    __shared__ float Bs[2][BKt][BNt];

    const int tid = threadIdx.x;
    const int bm = blockIdx.y * BMt;
    const int bn = blockIdx.x * BNt;
    const int tx = tid & 15;
    const int ty = tid >> 4;

    const int lrow = tid >> 2;
    const int lk   = (tid & 3) * 4;
    const int qsw  = (tid & 3);

    const float* aptr[2];
    float ascale[2];
    #pragma unroll
    for (int i = 0; i < 2; i++) {
        int gr = bm + lrow + 64 * i;
        if (gr < RROWS) { aptr[i] = Q + (size_t)gr * DIMV; ascale[i] = 1.0f; }
        else { int kr = gr - RROWS; aptr[i] = Kin + (size_t)kr * DIMV; ascale[i] = mask[kr]; }
    }
    const float* bptr = w + (size_t)(bn + lrow) * DIMV;

    float4 aReg[2], bReg;
    float acc[8][4];
    #pragma unroll
    for (int i = 0; i < 8; i++)
        #pragma unroll
        for (int j = 0; j < 4; j++) acc[i][j] = 0.0f;

    #pragma unroll
    for (int i = 0; i < 2; i++) {
        float4 v = *reinterpret_cast<const float4*>(aptr[i] + lk);
        v.x *= ascale[i]; v.y *= ascale[i]; v.z *= ascale[i]; v.w *= ascale[i];
        aReg[i] = v;
    }
    bReg = *reinterpret_cast<const float4*>(bptr + lk);
    {
        #pragma unroll
        for (int i = 0; i < 2; i++) {
            int row = lrow + 64 * i;
            int col = row ^ (qsw * 8);
            As[0][lk + 0][col] = aReg[i].x;
            As[0][lk + 1][col] = aReg[i].y;
            As[0][lk + 2][col] = aReg[i].z;
            As[0][lk + 3][col] = aReg[i].w;
        }
        int col = lrow ^ (qsw * 8);
        Bs[0][lk + 0][col] = bReg.x;
        Bs[0][lk + 1][col] = bReg.y;
        Bs[0][lk + 2][col] = bReg.z;
        Bs[0][lk + 3][col] = bReg.w;
    }
    __syncthreads();

    int buf = 0;
    const int NKT = DIMV / BKt;
    for (int kt = 0; kt < NKT; kt++) {
        if (kt < NKT - 1) {
            int k0 = (kt + 1) * BKt;
            #pragma unroll
            for (int i = 0; i < 2; i++) {
                float4 v = *reinterpret_cast<const float4*>(aptr[i] + k0 + lk);
                v.x *= ascale[i]; v.y *= ascale[i]; v.z *= ascale[i]; v.w *= ascale[i];
                aReg[i] = v;
            }
            bReg = *reinterpret_cast<const float4*>(bptr + k0 + lk);
        }
        #pragma unroll
        for (int k = 0; k < BKt; k++) {
            int qr = k >> 2;
            int cA = (ty ^ qr) * 8;
            float4 a0 = *reinterpret_cast<const float4*>(&As[buf][k][cA]);
            float4 a1 = *reinterpret_cast<const float4*>(&As[buf][k][cA + 4]);
            int cB = (tx * 4) ^ (qr * 8);
            float4 b0 = *reinterpret_cast<const float4*>(&Bs[buf][k][cB]);
            float av[8] = {a0.x, a0.y, a0.z, a0.w, a1.x, a1.y, a1.z, a1.w};
            float bv[4] = {b0.x, b0.y, b0.z, b0.w};
            #pragma unroll
            for (int i = 0; i < 8; i++)
                #pragma unroll
                for (int j = 0; j < 4; j++)
                    acc[i][j] = fmaf(av[i], bv[j], acc[i][j]);
        }
        if (kt < NKT - 1) {
            int nb = buf ^ 1;
            #pragma unroll
            for (int i = 0; i < 2; i++) {
                int row = lrow + 64 * i;
                int col = row ^ (qsw * 8);
                As[nb][lk + 0][col] = aReg[i].x;
                As[nb][lk + 1][col] = aReg[i].y;
                As[nb][lk + 2][col] = aReg[i].z;
                As[nb][lk + 3][col] = aReg[i].w;
            }
            int col = lrow ^ (qsw * 8);
            Bs[nb][lk + 0][col] = bReg.x;
            Bs[nb][lk + 1][col] = bReg.y;
            Bs[nb][lk + 2][col] = bReg.z;
            Bs[nb][lk + 3][col] = bReg.w;
            __syncthreads();
            buf = nb;
        }
    }

    #pragma unroll
    for (int i = 0; i < 8; i++) {
        int r = bm + ty * 8 + i;
        float xd = g_xd[r];
        float4 o;
        o.x = expf(acc[i][0] - xd) * RSQRTM;
        o.y = expf(acc[i][1] - xd) * RSQRTM;
        o.z = expf(acc[i][2] - xd) * RSQRTM;
        o.w = expf(acc[i][3] - xd) * RSQRTM;
        float* out = (r < RROWS) ? (g_qp + (size_t)r * MFEAT)
                                 : (g_kp + (size_t)(r - RROWS) * MFEAT);
        *reinterpret_cast<float4*>(out + bn + tx * 4) = o;
    }
}

__global__ void ksum_kernel() {
    if (g_flag == 0) return;
    int b = blockIdx.z;
    int m = blockIdx.x * 256 + threadIdx.x;
    float acc = 0.0f;
    for (int t = 0; t < TT; t++)
        acc += g_kp[((size_t)b * TT + t) * MFEAT + m];
    g_ksum[b * MFEAT + m] = acc;
}

__global__ void dvec_kernel() {
    if (g_flag == 0) return;
    int bt = blockIdx.x;
    int b = bt / TT;
    int tid = threadIdx.x;
    float acc = 0.0f;
    #pragma unroll
    for (int m = tid; m < MFEAT; m += 128)
        acc += g_qp[(size_t)bt * MFEAT + m] * g_ksum[b * MFEAT + m];
    #pragma unroll
    for (int o = 16; o; o >>= 1) acc += __shfl_xor_sync(0xFFFFFFFFu, acc, o);
    __shared__ float ws[4];
    if ((tid & 31) == 0) ws[tid >> 5] = acc;
    __syncthreads();
    if (tid == 0) g_D[bt] = ws[0] + ws[1] + ws[2] + ws[3];
}

__global__ void kptv_kernel(const float* __restrict__ V,
                            const float* __restrict__ mask) {
    if (g_flag == 0) return;
    __shared__ float Vs[16][17], Ks[16][17];
    int b = blockIdx.z;
    int n0 = blockIdx.y * 16, m0 = blockIdx.x * 16;
    int tx = threadIdx.x, ty = threadIdx.y;
    float acc = 0.0f;
    for (int t0 = 0; t0 < TT; t0 += 16) {
        int t = t0 + ty;
        Vs[ty][tx] = V[((size_t)b * TT + t) * DIMV + n0 + tx] * mask[b * TT + t];
        Ks[ty][tx] = g_kp[((size_t)b * TT + t) * MFEAT + m0 + tx];
        __syncthreads();
        #pragma unroll
        for (int kk = 0; kk < 16; kk++)
            acc = fmaf(Vs[kk][ty], Ks[kk][tx], acc);
        __syncthreads();
    }
    g_kptv[((size_t)b * DIMV + n0 + ty) * MFEAT + m0 + tx] = acc;
}

__global__ void y_full_kernel(float* __restrict__ out) {
    if (g_flag == 0) return;
    __shared__ float Qs[16][17], Ps[16][17];
    int b = blockIdx.z;
    int t0 = blockIdx.y * 16, n0 = blockIdx.x * 16;
    int tx = threadIdx.x, ty = threadIdx.y;
    float acc = 0.0f;
    for (int m0 = 0; m0 < MFEAT; m0 += 16) {
        Qs[ty][tx] = g_qp[((size_t)b * TT + t0 + ty) * MFEAT + m0 + tx];
        Ps[ty][tx] = g_kptv[((size_t)b * DIMV + n0 + ty) * MFEAT + m0 + tx];
        __syncthreads();
        #pragma unroll
        for (int kk = 0; kk < 16; kk++)
            acc = fmaf(Qs[ty][kk], Ps[tx][kk], acc);
        __syncthreads();
    }
    int t = t0 + ty;
    float inv = 1.0f / (g_D[b * TT + t] + EPSV);
    out[((size_t)b * TT + t) * DIMV + n0 + tx] = acc * inv * inv;
}

// zero writer (expected fast path: certificate passed)
__global__ void y_zero_kernel(float* __restrict__ out) {
    if (g_flag != 0) return;
    size_t idx = (size_t)blockIdx.x * blockDim.x + threadIdx.x;
    reinterpret_cast<float4*>(out)[idx] = make_float4(0.f, 0.f, 0.f, 0.f);
}

// ---------------- launch ----------------
extern "C" void kernel_launch(void* const* d_in, const int* in_sizes, int n_in,
                              void* d_out, int out_size) {
    const float* Q    = (const float*)d_in[0];
    const float* K    = (const float*)d_in[1];
    const float* V    = (const float*)d_in[2];
    const float* mask = (const float*)d_in[3];
    const float* w    = (const float*)d_in[4];
    float* out = (float*)d_out;
    (void)in_sizes; (void)n_in; (void)out_size;

    reset_kernel<<<1, 32>>>();
    xd_kernel<<<NROWS, 128>>>(Q, K, mask);
    wmax_kernel<<<MFEAT, 128>>>(w);
    cert_gemm<<<dim3(MFEAT / CN, NROWS / CM), 256>>>(Q, K, mask, w);

    // gated exact fallback (runs only if certificate failed)
    feat_gemm<<<dim3(MFEAT / BNt, NROWS / BMt), 256>>>(Q, K, mask, w);
    ksum_kernel<<<dim3(2, 1, BB), 256>>>();
    dvec_kernel<<<BB * TT, 128>>>();
    kptv_kernel<<<dim3(MFEAT / 16, DIMV / 16, BB), dim3(16, 16)>>>(V, mask);
    y_full_kernel<<<dim3(DIMV / 16, TT / 16, BB), dim3(16, 16)>>>(out);

    // fast path: provably-zero output
    y_zero_kernel<<<(RROWS * DIMV) / 4 / 256, 256>>>(out);
}

// round 4
// speedup vs baseline: 4.3739x; 1.6411x over previous
#include <cuda_runtime.h>
#include <cuda_bf16.h>
#include <math.h>
#include <stdint.h>

// ---------------- problem constants ----------------
#define BB      4
#define TT      4096
#define DIMV    1024
#define MFEAT   512
#define RROWS   (BB * TT)        // 16384 rows per tensor
#define NROWS   (2 * RROWS)      // 32768 X rows (Q then masked-K)
#define RSQRTM  0.04419417382415922f   // 1/sqrt(512)
#define EPSV    1e-8f

// ---------------- device scratch (static, allocation-free) ----------------
__device__ float g_qp[RROWS * MFEAT];       // fallback only (32 MB)
__device__ float g_kp[RROWS * MFEAT];       // fallback only (32 MB)
__device__ float g_xd[NROWS];
__device__ float g_ksum[BB * MFEAT];
__device__ float g_D[BB * TT];
__device__ float g_kptv[BB * DIMV * MFEAT]; // 8 MB
__device__ int   g_flag;                    // 1 => certificate failed -> exact path
__device__ int   g_wmaxsq_bits;
__device__ __nv_bfloat16 g_wbf[MFEAT * DIMV];    // 1 MB
__device__ __nv_bfloat16 g_xbf[(size_t)NROWS * DIMV]; // 64 MB

// ---------------- PTX helpers (sm_100-safe: mma.sync / ldmatrix / cp.async) --
__device__ __forceinline__ uint32_t smem_u32(const void* p) {
    return (uint32_t)__cvta_generic_to_shared(p);
}
__device__ __forceinline__ void ldmx4(uint32_t* r, uint32_t addr) {
    asm volatile("ldmatrix.sync.aligned.m8n8.x4.shared.b16 {%0,%1,%2,%3}, [%4];"
                 : "=r"(r[0]), "=r"(r[1]), "=r"(r[2]), "=r"(r[3]) : "r"(addr));
}
__device__ __forceinline__ void mma_bf16(float* c, const uint32_t* a, uint32_t b0, uint32_t b1) {
    asm volatile(
        "mma.sync.aligned.m16n8k16.row.col.f32.bf16.bf16.f32 "
        "{%0,%1,%2,%3},{%4,%5,%6,%7},{%8,%9},{%0,%1,%2,%3};"
        : "+f"(c[0]), "+f"(c[1]), "+f"(c[2]), "+f"(c[3])
        : "r"(a[0]), "r"(a[1]), "r"(a[2]), "r"(a[3]), "r"(b0), "r"(b1));
}
__device__ __forceinline__ void cp16(uint32_t dst, const void* src) {
    asm volatile("cp.async.cg.shared.global [%0], [%1], 16;" :: "r"(dst), "l"(src) : "memory");
}
#define CP_COMMIT() asm volatile("cp.async.commit_group;" ::: "memory")
#define CP_WAIT2()  asm volatile("cp.async.wait_group 2;" ::: "memory")

// 64B-per-row tile swizzle: chunk = 16B unit (0..3)
__device__ __forceinline__ int swz(int r, int chunk) {
    return r * 64 + ((chunk ^ ((r >> 1) & 3)) << 4);
}

// ---------------- kernel 0: reset flags ----------------
__global__ void reset_kernel() {
    if (threadIdx.x == 0) { g_flag = 0; g_wmaxsq_bits = 0; }
}

// ---------------- kernel 1: w -> bf16 + max row norm ----------------
__global__ void wconv_kernel(const float* __restrict__ w) {
    int m = blockIdx.x;
    int tid = threadIdx.x;  // 128
    const float4* p4 = reinterpret_cast<const float4*>(w + (size_t)m * DIMV);
    __nv_bfloat162* out = reinterpret_cast<__nv_bfloat162*>(g_wbf + (size_t)m * DIMV);
    float s = 0.0f;
    #pragma unroll
    for (int i = tid; i < DIMV / 4; i += 128) {
        float4 v = p4[i];
        s += v.x * v.x + v.y * v.y + v.z * v.z + v.w * v.w;
        out[i * 2 + 0] = __floats2bfloat162_rn(v.x, v.y);
        out[i * 2 + 1] = __floats2bfloat162_rn(v.z, v.w);
    }
    #pragma unroll
    for (int o = 16; o; o >>= 1) s += __shfl_xor_sync(0xFFFFFFFFu, s, o);
    __shared__ float ws[4];
    if ((tid & 31) == 0) ws[tid >> 5] = s;
    __syncthreads();
    if (tid == 0) atomicMax(&g_wmaxsq_bits, __float_as_int(ws[0] + ws[1] + ws[2] + ws[3]));
}

// ---------------- kernel 2: prep — X -> bf16, fused xd ----------------
// One warp per row: read f32 row (scale by mask), accumulate ||x||^2, write bf16.
__global__ void __launch_bounds__(256)
prep_kernel(const float* __restrict__ Q, const float* __restrict__ Kin,
            const float* __restrict__ mask) {
    int warp = threadIdx.x >> 5;
    int lane = threadIdx.x & 31;
    int grow = blockIdx.x * 8 + warp;          // 0..NROWS-1
    const float* src;
    float ms;
    if (grow < RROWS) { src = Q + (size_t)grow * DIMV; ms = 1.0f; }
    else { int kr = grow - RROWS; src = Kin + (size_t)kr * DIMV; ms = mask[kr]; }

    const float4* s4 = reinterpret_cast<const float4*>(src);
    uint2* o2 = reinterpret_cast<uint2*>(g_xbf + (size_t)grow * DIMV);
    float s = 0.0f;
    #pragma unroll
    for (int j = 0; j < 8; j++) {
        float4 v = s4[lane + 32 * j];
        v.x *= ms; v.y *= ms; v.z *= ms; v.w *= ms;
        s += v.x * v.x + v.y * v.y + v.z * v.z + v.w * v.w;
        __nv_bfloat162 lo = __floats2bfloat162_rn(v.x, v.y);
        __nv_bfloat162 hi = __floats2bfloat162_rn(v.z, v.w);
        uint2 u;
        u.x = *reinterpret_cast<unsigned*>(&lo);
        u.y = *reinterpret_cast<unsigned*>(&hi);
        o2[lane + 32 * j] = u;
    }
    #pragma unroll
    for (int o = 16; o; o >>= 1) s += __shfl_xor_sync(0xFFFFFFFFu, s, o);
    if (lane == 0) g_xd[grow] = 0.5f * s;
}

// ---------------- kernel 3: certificate GEMM (mma.sync bf16, cp.async) ------
// Block tile 128(M) x 128(N), K stage 32, 4-stage pipeline.
// 8 warps as 4(M) x 2(N): warp tile 32 x 64. Epilogue: threshold from regs.
#define CT_STAGE_BYTES 16384            // A 8KB + B 8KB
#define CT_DYN (4 * CT_STAGE_BYTES)     // 64 KB

extern __shared__ __align__(128) unsigned char ct_sm[];

__global__ void __launch_bounds__(256)
cert_gemm() {
    const int tid  = threadIdx.x;
    const int lane = tid & 31;
    const int warp = tid >> 5;
    const int wm = warp >> 1;            // 0..3 -> 32 M-rows
    const int wn = warp & 1;             // 0..1 -> 64 N-cols
    const int blockRow = blockIdx.y * 128;
    const int bn = blockIdx.x * 128;

    const uint32_t smb = smem_u32(ct_sm);

    // loader mapping: 2 halves of 64 rows; row = tid>>2, chunk(16B) = tid&3
    const int lrow = tid >> 2;           // 0..63
    const int lchunk = tid & 3;
    int offA[2], offB[2];
    const __nv_bfloat16* srcA[2];
    const __nv_bfloat16* srcB[2];
    #pragma unroll
    for (int h = 0; h < 2; h++) {
        int r = lrow + h * 64;
        offA[h] = swz(r, lchunk);
        offB[h] = swz(r, lchunk);
        srcA[h] = g_xbf + (size_t)(blockRow + r) * DIMV + lchunk * 8;
        srcB[h] = g_wbf + (size_t)(bn + r) * DIMV + lchunk * 8;
    }

    // ldmatrix addresses
    int lA[2][2], lB[4][2];
    #pragma unroll
    for (int kh = 0; kh < 2; kh++) {
        #pragma unroll
        for (int mi = 0; mi < 2; mi++)
            lA[mi][kh] = swz(wm * 32 + mi * 16 + (lane & 15), kh * 2 + (lane >> 4));
        #pragma unroll
        for (int i = 0; i < 4; i++)
            lB[i][kh] = swz(wn * 64 + i * 16 + (lane & 7) + ((lane >> 4) << 3),
                            kh * 2 + ((lane >> 3) & 1));
    }

    float acc[2][8][4];
    #pragma unroll
    for (int mi = 0; mi < 2; mi++)
        #pragma unroll
        for (int nj = 0; nj < 8; nj++)
            #pragma unroll
            for (int e = 0; e < 4; e++) acc[mi][nj][e] = 0.0f;

    // pipeline prologue: stages 0,1,2
    #pragma unroll
    for (int kt = 0; kt < 3; kt++) {
        uint32_t ab = smb + (kt & 3) * CT_STAGE_BYTES;
        uint32_t bb = ab + 8192;
        #pragma unroll
        for (int h = 0; h < 2; h++) {
            cp16(ab + offA[h], srcA[h] + kt * 32);
            cp16(bb + offB[h], srcB[h] + kt * 32);
        }
        CP_COMMIT();
    }

    const int NKT = DIMV / 32;           // 32
    for (int kt = 0; kt < NKT; kt++) {
        CP_WAIT2();
        __syncthreads();
        // issue stage kt+3 (slot previously held stage kt-1, consumed)
        if (kt + 3 < NKT) {
            int nk = kt + 3;
            uint32_t ab = smb + (nk & 3) * CT_STAGE_BYTES;
            uint32_t bb = ab + 8192;
            #pragma unroll
            for (int h = 0; h < 2; h++) {
                cp16(ab + offA[h], srcA[h] + nk * 32);
                cp16(bb + offB[h], srcB[h] + nk * 32);
            }
        }
        CP_COMMIT();

        uint32_t ab = smb + (kt & 3) * CT_STAGE_BYTES;
        uint32_t bb = ab + 8192;
        #pragma unroll
        for (int kh = 0; kh < 2; kh++) {
            uint32_t a0[4], a1[4], b[4][4];
            ldmx4(a0, ab + lA[0][kh]);
            ldmx4(a1, ab + lA[1][kh]);
            #pragma unroll
            for (int i = 0; i < 4; i++) ldmx4(b[i], bb + lB[i][kh]);
            #pragma unroll
            for (int i = 0; i < 4; i++) {
                mma_bf16(acc[0][2 * i],     a0, b[i][0], b[i][1]);
                mma_bf16(acc[0][2 * i + 1], a0, b[i][2], b[i][3]);
                mma_bf16(acc[1][2 * i],     a1, b[i][0], b[i][1]);
                mma_bf16(acc[1][2 * i + 1], a1, b[i][2], b[i][3]);
            }
        }
        __syncthreads();
    }

    // ---- epilogue: threshold check straight from registers ----
    bool bad = false;
    float wmaxsq = __int_as_float(g_wmaxsq_bits);
    if (!(wmaxsq <= 1250.0f)) bad = true;        // catches NaN too
    #pragma unroll
    for (int mi = 0; mi < 2; mi++) {
        int r0 = blockRow + wm * 32 + mi * 16 + (lane >> 2);
        float xd0 = g_xd[r0];
        float xd1 = g_xd[r0 + 8];
        if (!(xd0 <= 7000.0f) || !(xd1 <= 7000.0f)) bad = true;
        float t0 = xd0 - 160.0f;
        float t1 = xd1 - 160.0f;
        #pragma unroll
        for (int nj = 0; nj < 8; nj++) {
            if (!(acc[mi][nj][0] <= t0)) bad = true;
            if (!(acc[mi][nj][1] <= t0)) bad = true;
            if (!(acc[mi][nj][2] <= t1)) bad = true;
            if (!(acc[mi][nj][3] <= t1)) bad = true;
        }
    }
    if (__syncthreads_or(bad ? 1 : 0)) {
        if (tid == 0) atomicOr(&g_flag, 1);
    }
}

// ================= gated exact fp32 fallback (runs iff g_flag) ==============
#define BMt 128
#define BNt 64
#define BKt 16
__global__ void __launch_bounds__(256)
feat_gemm(const float* __restrict__ Q, const float* __restrict__ Kin,
          const float* __restrict__ mask, const float* __restrict__ w) {
    if (g_flag == 0) return;
    __shared__ float As[2][BKt][BMt];
    __shared__ float Bs[2][BKt][BNt];

    const int tid = threadIdx.x;
    const int bm = blockIdx.y * BMt;
    const int bn = blockIdx.x * BNt;
    const int tx = tid & 15;
    const int ty = tid >> 4;
    const int lrow = tid >> 2;
    const int lk   = (tid & 3) * 4;
    const int qsw  = (tid & 3);

    const float* aptr[2];
    float ascale[2];
    #pragma unroll
    for (int i = 0; i < 2; i++) {
        int gr = bm + lrow + 64 * i;
        if (gr < RROWS) { aptr[i] = Q + (size_t)gr * DIMV; ascale[i] = 1.0f; }
        else { int kr = gr - RROWS; aptr[i] = Kin + (size_t)kr * DIMV; ascale[i] = mask[kr]; }
    }
    const float* bptr = w + (size_t)(bn + lrow) * DIMV;

    float4 aReg[2], bReg;
    float acc[8][4];
    #pragma unroll
    for (int i = 0; i < 8; i++)
        #pragma unroll
        for (int j = 0; j < 4; j++) acc[i][j] = 0.0f;

    #pragma unroll
    for (int i = 0; i < 2; i++) {
        float4 v = *reinterpret_cast<const float4*>(aptr[i] + lk);
        v.x *= ascale[i]; v.y *= ascale[i]; v.z *= ascale[i]; v.w *= ascale[i];
        aReg[i] = v;
    }
    bReg = *reinterpret_cast<const float4*>(bptr + lk);
    {
        #pragma unroll
        for (int i = 0; i < 2; i++) {
            int row = lrow + 64 * i;
            int col = row ^ (qsw * 8);
            As[0][lk + 0][col] = aReg[i].x;
            As[0][lk + 1][col] = aReg[i].y;
            As[0][lk + 2][col] = aReg[i].z;
            As[0][lk + 3][col] = aReg[i].w;
        }
        int col = lrow ^ (qsw * 8);
        Bs[0][lk + 0][col] = bReg.x;
        Bs[0][lk + 1][col] = bReg.y;
        Bs[0][lk + 2][col] = bReg.z;
        Bs[0][lk + 3][col] = bReg.w;
    }
    __syncthreads();

    int buf = 0;
    const int NKT = DIMV / BKt;
    for (int kt = 0; kt < NKT; kt++) {
        if (kt < NKT - 1) {
            int k0 = (kt + 1) * BKt;
            #pragma unroll
            for (int i = 0; i < 2; i++) {
                float4 v = *reinterpret_cast<const float4*>(aptr[i] + k0 + lk);
                v.x *= ascale[i]; v.y *= ascale[i]; v.z *= ascale[i]; v.w *= ascale[i];
                aReg[i] = v;
            }
            bReg = *reinterpret_cast<const float4*>(bptr + k0 + lk);
        }
        #pragma unroll
        for (int k = 0; k < BKt; k++) {
            int qr = k >> 2;
            int cA = (ty ^ qr) * 8;
            float4 a0 = *reinterpret_cast<const float4*>(&As[buf][k][cA]);
            float4 a1 = *reinterpret_cast<const float4*>(&As[buf][k][cA + 4]);
            int cB = (tx * 4) ^ (qr * 8);
            float4 b0 = *reinterpret_cast<const float4*>(&Bs[buf][k][cB]);
            float av[8] = {a0.x, a0.y, a0.z, a0.w, a1.x, a1.y, a1.z, a1.w};
            float bv[4] = {b0.x, b0.y, b0.z, b0.w};
            #pragma unroll
            for (int i = 0; i < 8; i++)
                #pragma unroll
                for (int j = 0; j < 4; j++)
                    acc[i][j] = fmaf(av[i], bv[j], acc[i][j]);
        }
        if (kt < NKT - 1) {
            int nb = buf ^ 1;
            #pragma unroll
            for (int i = 0; i < 2; i++) {
                int row = lrow + 64 * i;
                int col = row ^ (qsw * 8);
                As[nb][lk + 0][col] = aReg[i].x;
                As[nb][lk + 1][col] = aReg[i].y;
                As[nb][lk + 2][col] = aReg[i].z;
                As[nb][lk + 3][col] = aReg[i].w;
            }
            int col = lrow ^ (qsw * 8);
            Bs[nb][lk + 0][col] = bReg.x;
            Bs[nb][lk + 1][col] = bReg.y;
            Bs[nb][lk + 2][col] = bReg.z;
            Bs[nb][lk + 3][col] = bReg.w;
            __syncthreads();
            buf = nb;
        }
    }
    #pragma unroll
    for (int i = 0; i < 8; i++) {
        int r = bm + ty * 8 + i;
        float xd = g_xd[r];
        float4 o;
        o.x = expf(acc[i][0] - xd) * RSQRTM;
        o.y = expf(acc[i][1] - xd) * RSQRTM;
        o.z = expf(acc[i][2] - xd) * RSQRTM;
        o.w = expf(acc[i][3] - xd) * RSQRTM;
        float* out = (r < RROWS) ? (g_qp + (size_t)r * MFEAT)
                                 : (g_kp + (size_t)(r - RROWS) * MFEAT);
        *reinterpret_cast<float4*>(out + bn + tx * 4) = o;
    }
}

__global__ void ksum_kernel() {
    if (g_flag == 0) return;
    int b = blockIdx.z;
    int m = blockIdx.x * 256 + threadIdx.x;
    float acc = 0.0f;
    for (int t = 0; t < TT; t++)
        acc += g_kp[((size_t)b * TT + t) * MFEAT + m];
    g_ksum[b * MFEAT + m] = acc;
}

__global__ void dvec_kernel() {
    if (g_flag == 0) return;
    int bt = blockIdx.x;
    int b = bt / TT;
    int tid = threadIdx.x;
    float acc = 0.0f;
    #pragma unroll
    for (int m = tid; m < MFEAT; m += 128)
        acc += g_qp[(size_t)bt * MFEAT + m] * g_ksum[b * MFEAT + m];
    #pragma unroll
    for (int o = 16; o; o >>= 1) acc += __shfl_xor_sync(0xFFFFFFFFu, acc, o);
    __shared__ float ws[4];
    if ((tid & 31) == 0) ws[tid >> 5] = acc;
    __syncthreads();
    if (tid == 0) g_D[bt] = ws[0] + ws[1] + ws[2] + ws[3];
}

__global__ void kptv_kernel(const float* __restrict__ V,
                            const float* __restrict__ mask) {
    if (g_flag == 0) return;
    __shared__ float Vs[16][17], Ks[16][17];
    int b = blockIdx.z;
    int n0 = blockIdx.y * 16, m0 = blockIdx.x * 16;
    int tx = threadIdx.x, ty = threadIdx.y;
    float acc = 0.0f;
    for (int t0 = 0; t0 < TT; t0 += 16) {
        int t = t0 + ty;
        Vs[ty][tx] = V[((size_t)b * TT + t) * DIMV + n0 + tx] * mask[b * TT + t];
        Ks[ty][tx] = g_kp[((size_t)b * TT + t) * MFEAT + m0 + tx];
        __syncthreads();
        #pragma unroll
        for (int kk = 0; kk < 16; kk++)
            acc = fmaf(Vs[kk][ty], Ks[kk][tx], acc);
        __syncthreads();
    }
    g_kptv[((size_t)b * DIMV + n0 + ty) * MFEAT + m0 + tx] = acc;
}

__global__ void y_full_kernel(float* __restrict__ out) {
    if (g_flag == 0) return;
    __shared__ float Qs[16][17], Ps[16][17];
    int b = blockIdx.z;
    int t0 = blockIdx.y * 16, n0 = blockIdx.x * 16;
    int tx = threadIdx.x, ty = threadIdx.y;
    float acc = 0.0f;
    for (int m0 = 0; m0 < MFEAT; m0 += 16) {
        Qs[ty][tx] = g_qp[((size_t)b * TT + t0 + ty) * MFEAT + m0 + tx];
        Ps[ty][tx] = g_kptv[((size_t)b * DIMV + n0 + ty) * MFEAT + m0 + tx];
        __syncthreads();
        #pragma unroll
        for (int kk = 0; kk < 16; kk++)
            acc = fmaf(Qs[ty][kk], Ps[tx][kk], acc);
        __syncthreads();
    }
    int t = t0 + ty;
    float inv = 1.0f / (g_D[b * TT + t] + EPSV);
    out[((size_t)b * TT + t) * DIMV + n0 + tx] = acc * inv * inv;
}

__global__ void y_zero_kernel(float* __restrict__ out) {
    if (g_flag != 0) return;
    size_t idx = (size_t)blockIdx.x * blockDim.x + threadIdx.x;
    reinterpret_cast<float4*>(out)[idx] = make_float4(0.f, 0.f, 0.f, 0.f);
}

// ---------------- launch ----------------
extern "C" void kernel_launch(void* const* d_in, const int* in_sizes, int n_in,
                              void* d_out, int out_size) {
    const float* Q    = (const float*)d_in[0];
    const float* K    = (const float*)d_in[1];
    const float* V    = (const float*)d_in[2];
    const float* mask = (const float*)d_in[3];
    const float* w    = (const float*)d_in[4];
    float* out = (float*)d_out;
    (void)in_sizes; (void)n_in; (void)out_size;

    cudaFuncSetAttribute(cert_gemm, cudaFuncAttributeMaxDynamicSharedMemorySize, CT_DYN);

    reset_kernel<<<1, 32>>>();
    wconv_kernel<<<MFEAT, 128>>>(w);
    prep_kernel<<<NROWS / 8, 256>>>(Q, K, mask);
    cert_gemm<<<dim3(MFEAT / 128, NROWS / 128), 256, CT_DYN>>>();

    // gated exact fallback
    feat_gemm<<<dim3(MFEAT / BNt, NROWS / BMt), 256>>>(Q, K, mask, w);
    ksum_kernel<<<dim3(2, 1, BB), 256>>>();
    dvec_kernel<<<BB * TT, 128>>>();
    kptv_kernel<<<dim3(MFEAT / 16, DIMV / 16, BB), dim3(16, 16)>>>(V, mask);
    y_full_kernel<<<dim3(DIMV / 16, TT / 16, BB), dim3(16, 16)>>>(out);

    // fast path: provably-zero output
    y_zero_kernel<<<(RROWS * DIMV) / 4 / 256, 256>>>(out);
}

// round 6
// speedup vs baseline: 4.7447x; 1.0848x over previous
#include <cuda_runtime.h>
#include <cuda_bf16.h>
#include <math.h>
#include <stdint.h>

// ---------------- problem constants ----------------
#define BB      4
#define TT      4096
#define DIMV    1024
#define MFEAT   512
#define RROWS   (BB * TT)        // 16384 rows per tensor
#define NROWS   (2 * RROWS)      // 32768 X rows (Q then masked-K)
#define RSQRTM  0.04419417382415922f
#define EPSV    1e-8f

// ---------------- device scratch (static, allocation-free) ----------------
__device__ float g_qp[RROWS * MFEAT];       // fallback only (32 MB)
__device__ float g_kp[RROWS * MFEAT];       // fallback only (32 MB)
__device__ float g_xd[NROWS];
__device__ float g_ksum[BB * MFEAT];
__device__ float g_D[BB * TT];
__device__ float g_kptv[BB * DIMV * MFEAT]; // 8 MB
__device__ int   g_flag;                    // 1 => certificate failed -> exact path
__device__ float g_wnorm[MFEAT];            // per-row ||w_m||^2
__device__ unsigned char g_wq8[MFEAT * DIMV];        // w as e4m3 (512 KB)
__device__ unsigned char g_xq8[(size_t)NROWS * DIMV]; // X as e4m3 (32 MB)

// ---------------- PTX helpers (sm_100-safe) ----------------
__device__ __forceinline__ uint32_t smem_u32(const void* p) {
    return (uint32_t)__cvta_generic_to_shared(p);
}
__device__ __forceinline__ void ldmx4(uint32_t* r, uint32_t addr) {
    asm volatile("ldmatrix.sync.aligned.m8n8.x4.shared.b16 {%0,%1,%2,%3}, [%4];"
                 : "=r"(r[0]), "=r"(r[1]), "=r"(r[2]), "=r"(r[3]) : "r"(addr));
}
__device__ __forceinline__ void mma_fp8(float* c, const uint32_t* a, uint32_t b0, uint32_t b1) {
    asm volatile(
        "mma.sync.aligned.m16n8k32.row.col.f32.e4m3.e4m3.f32 "
        "{%0,%1,%2,%3},{%4,%5,%6,%7},{%8,%9},{%0,%1,%2,%3};"
        : "+f"(c[0]), "+f"(c[1]), "+f"(c[2]), "+f"(c[3])
        : "r"(a[0]), "r"(a[1]), "r"(a[2]), "r"(a[3]), "r"(b0), "r"(b1));
}
__device__ __forceinline__ void cp16(uint32_t dst, const void* src) {
    asm volatile("cp.async.cg.shared.global [%0], [%1], 16;" :: "r"(dst), "l"(src) : "memory");
}
#define CP_COMMIT() asm volatile("cp.async.commit_group;" ::: "memory")
#define CP_WAIT2()  asm volatile("cp.async.wait_group 2;" ::: "memory")

// pack 4 floats -> 4 e4m3 bytes (cvt dest is .b16 -> use "h" constraints)
__device__ __forceinline__ uint32_t pack_e4m3x4(float4 v) {
    uint16_t lo, hi;
    asm("cvt.rn.satfinite.e4m3x2.f32 %0, %1, %2;" : "=h"(lo) : "f"(v.y), "f"(v.x));
    asm("cvt.rn.satfinite.e4m3x2.f32 %0, %1, %2;" : "=h"(hi) : "f"(v.w), "f"(v.z));
    return ((uint32_t)hi << 16) | (uint32_t)lo;
}

// 64B-per-row tile swizzle: chunk = 16B unit (0..3)
__device__ __forceinline__ int swz(int r, int chunk) {
    return r * 64 + ((chunk ^ ((r >> 1) & 3)) << 4);
}

// ---------------- kernel 1: w -> e4m3 + per-row norms (+ flag reset) --------
__global__ void wconv_kernel(const float* __restrict__ w) {
    int m = blockIdx.x;            // 0..511
    int tid = threadIdx.x;         // 128
    if (m == 0 && tid == 0) g_flag = 0;
    const float4* p4 = reinterpret_cast<const float4*>(w + (size_t)m * DIMV);
    uint32_t* out = reinterpret_cast<uint32_t*>(g_wq8 + (size_t)m * DIMV);
    float s = 0.0f;
    #pragma unroll
    for (int i = tid; i < DIMV / 4; i += 128) {
        float4 v = p4[i];
        s += v.x * v.x + v.y * v.y + v.z * v.z + v.w * v.w;
        out[i] = pack_e4m3x4(v);
    }
    #pragma unroll
    for (int o = 16; o; o >>= 1) s += __shfl_xor_sync(0xFFFFFFFFu, s, o);
    __shared__ float ws[4];
    if ((tid & 31) == 0) ws[tid >> 5] = s;
    __syncthreads();
    if (tid == 0) g_wnorm[m] = ws[0] + ws[1] + ws[2] + ws[3];
}

// ---------------- kernel 2: prep — X -> e4m3, fused xd, zero out ------------
__global__ void __launch_bounds__(256)
prep_kernel(const float* __restrict__ Q, const float* __restrict__ Kin,
            const float* __restrict__ mask, float* __restrict__ out) {
    int warp = threadIdx.x >> 5;
    int lane = threadIdx.x & 31;
    int grow = blockIdx.x * 8 + warp;          // 0..NROWS-1
    const float* src;
    float ms;
    if (grow < RROWS) { src = Q + (size_t)grow * DIMV; ms = 1.0f; }
    else { int kr = grow - RROWS; src = Kin + (size_t)kr * DIMV; ms = mask[kr]; }

    const float4* s4 = reinterpret_cast<const float4*>(src);
    uint32_t* o4 = reinterpret_cast<uint32_t*>(g_xq8 + (size_t)grow * DIMV);
    float s = 0.0f;
    #pragma unroll
    for (int j = 0; j < 8; j++) {
        float4 v = s4[lane + 32 * j];
        v.x *= ms; v.y *= ms; v.z *= ms; v.w *= ms;
        s += v.x * v.x + v.y * v.y + v.z * v.z + v.w * v.w;
        o4[lane + 32 * j] = pack_e4m3x4(v);
    }
    #pragma unroll
    for (int o = 16; o; o >>= 1) s += __shfl_xor_sync(0xFFFFFFFFu, s, o);
    if (lane == 0) g_xd[grow] = 0.5f * s;

    // unconditional zero of the output slice (fallback overwrites if flagged)
    float4* oz = reinterpret_cast<float4*>(out) + (size_t)blockIdx.x * 1024;
    #pragma unroll
    for (int j = 0; j < 4; j++)
        oz[threadIdx.x + 256 * j] = make_float4(0.f, 0.f, 0.f, 0.f);
}

// ---------------- kernel 3: fp8 certificate GEMM ----------------------------
// Block 128(M) x 128(N), K stage 64 fp8, 4-stage cp.async pipeline.
// 8 warps 4x2, warp tile 32x64. Epilogue: per-row threshold from registers.
#define CT_STAGE_BYTES 16384            // A 8KB + B 8KB
#define CT_DYN (4 * CT_STAGE_BYTES)     // 64 KB

extern __shared__ __align__(128) unsigned char ct_sm[];

__global__ void __launch_bounds__(256, 2)
cert_gemm() {
    const int tid  = threadIdx.x;
    const int lane = tid & 31;
    const int warp = tid >> 5;
    const int wm = warp >> 1;
    const int wn = warp & 1;
    const int blockRow = blockIdx.y * 128;
    const int bn = blockIdx.x * 128;

    const uint32_t smb = smem_u32(ct_sm);

    // loaders: 64 rows per pass (2 passes), 16B chunk per thread
    const int lrow = tid >> 2;           // 0..63
    const int lchunk = tid & 3;
    int offA[2], offB[2];
    const unsigned char* srcA[2];
    const unsigned char* srcB[2];
    #pragma unroll
    for (int h = 0; h < 2; h++) {
        int r = lrow + h * 64;
        offA[h] = swz(r, lchunk);
        offB[h] = swz(r, lchunk);
        srcA[h] = g_xq8 + (size_t)(blockRow + r) * DIMV + lchunk * 16;
        srcB[h] = g_wq8 + (size_t)(bn + r) * DIMV + lchunk * 16;
    }

    // ldmatrix addresses (k32-half kh uses 16B chunks kh*2 + {0,1})
    int lA[2][2], lB[4][2];
    #pragma unroll
    for (int kh = 0; kh < 2; kh++) {
        #pragma unroll
        for (int mi = 0; mi < 2; mi++)
            lA[mi][kh] = swz(wm * 32 + mi * 16 + (lane & 15), kh * 2 + (lane >> 4));
        #pragma unroll
        for (int i = 0; i < 4; i++)
            lB[i][kh] = swz(wn * 64 + i * 16 + (lane & 7) + ((lane >> 4) << 3),
                            kh * 2 + ((lane >> 3) & 1));
    }

    float acc[2][8][4];
    #pragma unroll
    for (int mi = 0; mi < 2; mi++)
        #pragma unroll
        for (int nj = 0; nj < 8; nj++)
            #pragma unroll
            for (int e = 0; e < 4; e++) acc[mi][nj][e] = 0.0f;

    // prologue: stages 0..2
    #pragma unroll
    for (int kt = 0; kt < 3; kt++) {
        uint32_t ab = smb + (kt & 3) * CT_STAGE_BYTES;
        uint32_t bb = ab + 8192;
        #pragma unroll
        for (int h = 0; h < 2; h++) {
            cp16(ab + offA[h], srcA[h] + kt * 64);
            cp16(bb + offB[h], srcB[h] + kt * 64);
        }
        CP_COMMIT();
    }

    const int NKT = DIMV / 64;           // 16 stages
    for (int kt = 0; kt < NKT; kt++) {
        CP_WAIT2();
        __syncthreads();
        if (kt + 3 < NKT) {
            int nk = kt + 3;
            uint32_t ab = smb + (nk & 3) * CT_STAGE_BYTES;
            uint32_t bb = ab + 8192;
            #pragma unroll
            for (int h = 0; h < 2; h++) {
                cp16(ab + offA[h], srcA[h] + nk * 64);
                cp16(bb + offB[h], srcB[h] + nk * 64);
            }
        }
        CP_COMMIT();

        uint32_t ab = smb + (kt & 3) * CT_STAGE_BYTES;
        uint32_t bb = ab + 8192;
        #pragma unroll
        for (int kh = 0; kh < 2; kh++) {
            uint32_t a0[4], a1[4], b[4][4];
            ldmx4(a0, ab + lA[0][kh]);
            ldmx4(a1, ab + lA[1][kh]);
            #pragma unroll
            for (int i = 0; i < 4; i++) ldmx4(b[i], bb + lB[i][kh]);
            #pragma unroll
            for (int i = 0; i < 4; i++) {
                mma_fp8(acc[0][2 * i],     a0, b[i][0], b[i][1]);
                mma_fp8(acc[0][2 * i + 1], a0, b[i][2], b[i][3]);
                mma_fp8(acc[1][2 * i],     a1, b[i][0], b[i][1]);
                mma_fp8(acc[1][2 * i + 1], a1, b[i][2], b[i][3]);
            }
        }
        __syncthreads();
    }

    // ---- epilogue: rigor guards + per-row fp8 threshold ----
    bool bad = false;
    // guard: every ||w_m||^2 <= 1250 (each thread checks 2 entries)
    if (!(g_wnorm[tid] <= 1250.0f)) bad = true;
    if (!(g_wnorm[tid + 256] <= 1250.0f)) bad = true;
    #pragma unroll
    for (int mi = 0; mi < 2; mi++) {
        int r0 = blockRow + wm * 32 + mi * 16 + (lane >> 2);
        float xd0 = g_xd[r0];
        float xd1 = g_xd[r0 + 8];
        if (!(xd0 <= 7000.0f) || !(xd1 <= 7000.0f)) bad = true;   // catches NaN
        // fp8 error bound: 0.13*||x||*||w|| + accum slack <= 6.5*sqrt(xd) + 8
        float t0 = xd0 - 118.0f - 6.5f * sqrtf(fmaxf(xd0, 0.0f));
        float t1 = xd1 - 118.0f - 6.5f * sqrtf(fmaxf(xd1, 0.0f));
        #pragma unroll
        for (int nj = 0; nj < 8; nj++) {
            if (!(acc[mi][nj][0] <= t0)) bad = true;
            if (!(acc[mi][nj][1] <= t0)) bad = true;
            if (!(acc[mi][nj][2] <= t1)) bad = true;
            if (!(acc[mi][nj][3] <= t1)) bad = true;
        }
    }
    if (__syncthreads_or(bad ? 1 : 0)) {
        if (tid == 0) atomicOr(&g_flag, 1);
    }
}

// ================= gated exact fp32 fallback (runs iff g_flag) ==============
#define BMt 128
#define BNt 64
#define BKt 16
__global__ void __launch_bounds__(256)
feat_gemm(const float* __restrict__ Q, const float* __restrict__ Kin,
          const float* __restrict__ mask, const float* __restrict__ w) {
    if (g_flag == 0) return;
    __shared__ float As[2][BKt][BMt];
    __shared__ float Bs[2][BKt][BNt];

    const int tid = threadIdx.x;
    const int bm = blockIdx.y * BMt;
    const int bn = blockIdx.x * BNt;
    const int tx = tid & 15;
    const int ty = tid >> 4;
    const int lrow = tid >> 2;
    const int lk   = (tid & 3) * 4;
    const int qsw  = (tid & 3);

    const float* aptr[2];
    float ascale[2];
    #pragma unroll
    for (int i = 0; i < 2; i++) {
        int gr = bm + lrow + 64 * i;
        if (gr < RROWS) { aptr[i] = Q + (size_t)gr * DIMV; ascale[i] = 1.0f; }
        else { int kr = gr - RROWS; aptr[i] = Kin + (size_t)kr * DIMV; ascale[i] = mask[kr]; }
    }
    const float* bptr = w + (size_t)(bn + lrow) * DIMV;

    float4 aReg[2], bReg;
    float acc[8][4];
    #pragma unroll
    for (int i = 0; i < 8; i++)
        #pragma unroll
        for (int j = 0; j < 4; j++) acc[i][j] = 0.0f;

    #pragma unroll
    for (int i = 0; i < 2; i++) {
        float4 v = *reinterpret_cast<const float4*>(aptr[i] + lk);
        v.x *= ascale[i]; v.y *= ascale[i]; v.z *= ascale[i]; v.w *= ascale[i];
        aReg[i] = v;
    }
    bReg = *reinterpret_cast<const float4*>(bptr + lk);
    {
        #pragma unroll
        for (int i = 0; i < 2; i++) {
            int row = lrow + 64 * i;
            int col = row ^ (qsw * 8);
            As[0][lk + 0][col] = aReg[i].x;
            As[0][lk + 1][col] = aReg[i].y;
            As[0][lk + 2][col] = aReg[i].z;
            As[0][lk + 3][col] = aReg[i].w;
        }
        int col = lrow ^ (qsw * 8);
        Bs[0][lk + 0][col] = bReg.x;
        Bs[0][lk + 1][col] = bReg.y;
        Bs[0][lk + 2][col] = bReg.z;
        Bs[0][lk + 3][col] = bReg.w;
    }
    __syncthreads();

    int buf = 0;
    const int NKT = DIMV / BKt;
    for (int kt = 0; kt < NKT; kt++) {
        if (kt < NKT - 1) {
            int k0 = (kt + 1) * BKt;
            #pragma unroll
            for (int i = 0; i < 2; i++) {
                float4 v = *reinterpret_cast<const float4*>(aptr[i] + k0 + lk);
                v.x *= ascale[i]; v.y *= ascale[i]; v.z *= ascale[i]; v.w *= ascale[i];
                aReg[i] = v;
            }
            bReg = *reinterpret_cast<const float4*>(bptr + k0 + lk);
        }
        #pragma unroll
        for (int k = 0; k < BKt; k++) {
            int qr = k >> 2;
            int cA = (ty ^ qr) * 8;
            float4 a0 = *reinterpret_cast<const float4*>(&As[buf][k][cA]);
            float4 a1 = *reinterpret_cast<const float4*>(&As[buf][k][cA + 4]);
            int cB = (tx * 4) ^ (qr * 8);
            float4 b0 = *reinterpret_cast<const float4*>(&Bs[buf][k][cB]);
            float av[8] = {a0.x, a0.y, a0.z, a0.w, a1.x, a1.y, a1.z, a1.w};
            float bv[4] = {b0.x, b0.y, b0.z, b0.w};
            #pragma unroll
            for (int i = 0; i < 8; i++)
                #pragma unroll
                for (int j = 0; j < 4; j++)
                    acc[i][j] = fmaf(av[i], bv[j], acc[i][j]);
        }
        if (kt < NKT - 1) {
            int nb = buf ^ 1;
            #pragma unroll
            for (int i = 0; i < 2; i++) {
                int row = lrow + 64 * i;
                int col = row ^ (qsw * 8);
                As[nb][lk + 0][col] = aReg[i].x;
                As[nb][lk + 1][col] = aReg[i].y;
                As[nb][lk + 2][col] = aReg[i].z;
                As[nb][lk + 3][col] = aReg[i].w;
            }
            int col = lrow ^ (qsw * 8);
            Bs[nb][lk + 0][col] = bReg.x;
            Bs[nb][lk + 1][col] = bReg.y;
            Bs[nb][lk + 2][col] = bReg.z;
            Bs[nb][lk + 3][col] = bReg.w;
            __syncthreads();
            buf = nb;
        }
    }
    #pragma unroll
    for (int i = 0; i < 8; i++) {
        int r = bm + ty * 8 + i;
        float xd = g_xd[r];
        float4 o;
        o.x = expf(acc[i][0] - xd) * RSQRTM;
        o.y = expf(acc[i][1] - xd) * RSQRTM;
        o.z = expf(acc[i][2] - xd) * RSQRTM;
        o.w = expf(acc[i][3] - xd) * RSQRTM;
        float* out = (r < RROWS) ? (g_qp + (size_t)r * MFEAT)
                                 : (g_kp + (size_t)(r - RROWS) * MFEAT);
        *reinterpret_cast<float4*>(out + bn + tx * 4) = o;
    }
}

__global__ void ksum_kernel() {
    if (g_flag == 0) return;
    int b = blockIdx.z;
    int m = blockIdx.x * 256 + threadIdx.x;
    float acc = 0.0f;
    for (int t = 0; t < TT; t++)
        acc += g_kp[((size_t)b * TT + t) * MFEAT + m];
    g_ksum[b * MFEAT + m] = acc;
}

__global__ void dvec_kernel() {
    if (g_flag == 0) return;
    int bt = blockIdx.x;
    int b = bt / TT;
    int tid = threadIdx.x;
    float acc = 0.0f;
    #pragma unroll
    for (int m = tid; m < MFEAT; m += 128)
        acc += g_qp[(size_t)bt * MFEAT + m] * g_ksum[b * MFEAT + m];
    #pragma unroll
    for (int o = 16; o; o >>= 1) acc += __shfl_xor_sync(0xFFFFFFFFu, acc, o);
    __shared__ float ws[4];
    if ((tid & 31) == 0) ws[tid >> 5] = acc;
    __syncthreads();
    if (tid == 0) g_D[bt] = ws[0] + ws[1] + ws[2] + ws[3];
}

__global__ void kptv_kernel(const float* __restrict__ V,
                            const float* __restrict__ mask) {
    if (g_flag == 0) return;
    __shared__ float Vs[16][17], Ks[16][17];
    int b = blockIdx.z;
    int n0 = blockIdx.y * 16, m0 = blockIdx.x * 16;
    int tx = threadIdx.x, ty = threadIdx.y;
    float acc = 0.0f;
    for (int t0 = 0; t0 < TT; t0 += 16) {
        int t = t0 + ty;
        Vs[ty][tx] = V[((size_t)b * TT + t) * DIMV + n0 + tx] * mask[b * TT + t];
        Ks[ty][tx] = g_kp[((size_t)b * TT + t) * MFEAT + m0 + tx];
        __syncthreads();
        #pragma unroll
        for (int kk = 0; kk < 16; kk++)
            acc = fmaf(Vs[kk][ty], Ks[kk][tx], acc);
        __syncthreads();
    }
    g_kptv[((size_t)b * DIMV + n0 + ty) * MFEAT + m0 + tx] = acc;
}

__global__ void y_full_kernel(float* __restrict__ out) {
    if (g_flag == 0) return;
    __shared__ float Qs[16][17], Ps[16][17];
    int b = blockIdx.z;
    int t0 = blockIdx.y * 16, n0 = blockIdx.x * 16;
    int tx = threadIdx.x, ty = threadIdx.y;
    float acc = 0.0f;
    for (int m0 = 0; m0 < MFEAT; m0 += 16) {
        Qs[ty][tx] = g_qp[((size_t)b * TT + t0 + ty) * MFEAT + m0 + tx];
        Ps[ty][tx] = g_kptv[((size_t)b * DIMV + n0 + ty) * MFEAT + m0 + tx];
        __syncthreads();
        #pragma unroll
        for (int kk = 0; kk < 16; kk++)
            acc = fmaf(Qs[ty][kk], Ps[tx][kk], acc);
        __syncthreads();
    }
    int t = t0 + ty;
    float inv = 1.0f / (g_D[b * TT + t] + EPSV);
    out[((size_t)b * TT + t) * DIMV + n0 + tx] = acc * inv * inv;
}

// ---------------- launch ----------------
extern "C" void kernel_launch(void* const* d_in, const int* in_sizes, int n_in,
                              void* d_out, int out_size) {
    const float* Q    = (const float*)d_in[0];
    const float* K    = (const float*)d_in[1];
    const float* V    = (const float*)d_in[2];
    const float* mask = (const float*)d_in[3];
    const float* w    = (const float*)d_in[4];
    float* out = (float*)d_out;
    (void)in_sizes; (void)n_in; (void)out_size;

    cudaFuncSetAttribute(cert_gemm, cudaFuncAttributeMaxDynamicSharedMemorySize, CT_DYN);

    wconv_kernel<<<MFEAT, 128>>>(w);
    prep_kernel<<<NROWS / 8, 256>>>(Q, K, mask, out);
    cert_gemm<<<dim3(MFEAT / 128, NROWS / 128), 256, CT_DYN>>>();

    // gated exact fallback (no-ops when certificate passed)
    feat_gemm<<<dim3(MFEAT / BNt, NROWS / BMt), 256>>>(Q, K, mask, w);
    ksum_kernel<<<dim3(2, 1, BB), 256>>>();
    dvec_kernel<<<BB * TT, 128>>>();
    kptv_kernel<<<dim3(MFEAT / 16, DIMV / 16, BB), dim3(16, 16)>>>(V, mask);
    y_full_kernel<<<dim3(DIMV / 16, TT / 16, BB), dim3(16, 16)>>>(out);
}

// round 7
// speedup vs baseline: 6.3067x; 1.3292x over previous
#include <cuda_runtime.h>
#include <cuda_bf16.h>
#include <math.h>
#include <stdint.h>

// ---------------- problem constants ----------------
#define BB      4
#define TT      4096
#define DIMV    1024
#define MFEAT   512
#define RROWS   (BB * TT)        // 16384 rows per tensor
#define NROWS   (2 * RROWS)      // 32768 X rows (Q then masked-K)
#define RSQRTM  0.04419417382415922f
#define EPSV    1e-8f

// ---------------- device scratch (static, allocation-free) ----------------
__device__ float g_qp[RROWS * MFEAT];       // fallback only (32 MB)
__device__ float g_kp[RROWS * MFEAT];       // fallback only (32 MB)
__device__ float g_xd[NROWS];
__device__ float g_ksum[BB * MFEAT];
__device__ float g_D[BB * TT];
__device__ float g_kptv[BB * DIMV * MFEAT]; // 8 MB
__device__ int   g_flag;                    // 1 => certificate failed -> exact path
__device__ float g_wnorm[MFEAT];            // per-row ||w_m||^2
__device__ unsigned char g_wq8[MFEAT * DIMV];        // w as e4m3 (512 KB)
__device__ unsigned char g_xq8[(size_t)NROWS * DIMV]; // X as e4m3 (32 MB)

// ---------------- PTX helpers (sm_100-safe) ----------------
__device__ __forceinline__ uint32_t smem_u32(const void* p) {
    return (uint32_t)__cvta_generic_to_shared(p);
}
__device__ __forceinline__ void ldmx4(uint32_t* r, uint32_t addr) {
    asm volatile("ldmatrix.sync.aligned.m8n8.x4.shared.b16 {%0,%1,%2,%3}, [%4];"
                 : "=r"(r[0]), "=r"(r[1]), "=r"(r[2]), "=r"(r[3]) : "r"(addr));
}
__device__ __forceinline__ void mma_fp8(float* c, const uint32_t* a, uint32_t b0, uint32_t b1) {
    asm volatile(
        "mma.sync.aligned.m16n8k32.row.col.f32.e4m3.e4m3.f32 "
        "{%0,%1,%2,%3},{%4,%5,%6,%7},{%8,%9},{%0,%1,%2,%3};"
        : "+f"(c[0]), "+f"(c[1]), "+f"(c[2]), "+f"(c[3])
        : "r"(a[0]), "r"(a[1]), "r"(a[2]), "r"(a[3]), "r"(b0), "r"(b1));
}
__device__ __forceinline__ void cp16(uint32_t dst, const void* src) {
    asm volatile("cp.async.cg.shared.global [%0], [%1], 16;" :: "r"(dst), "l"(src) : "memory");
}
#define CP_COMMIT() asm volatile("cp.async.commit_group;" ::: "memory")
#define CP_WAIT2()  asm volatile("cp.async.wait_group 2;" ::: "memory")

// pack 4 floats -> 4 e4m3 bytes
__device__ __forceinline__ uint32_t pack_e4m3x4(float4 v) {
    uint16_t lo, hi;
    asm("cvt.rn.satfinite.e4m3x2.f32 %0, %1, %2;" : "=h"(lo) : "f"(v.y), "f"(v.x));
    asm("cvt.rn.satfinite.e4m3x2.f32 %0, %1, %2;" : "=h"(hi) : "f"(v.w), "f"(v.z));
    return ((uint32_t)hi << 16) | (uint32_t)lo;
}

// 64B-per-row tile swizzle: chunk = 16B unit (0..3)
__device__ __forceinline__ int swz(int r, int chunk) {
    return r * 64 + ((chunk ^ ((r >> 1) & 3)) << 4);
}

// ---------------- kernel 1: w -> e4m3 + per-row norms (+ flag reset) --------
__global__ void wconv_kernel(const float* __restrict__ w) {
    int m = blockIdx.x;            // 0..511
    int tid = threadIdx.x;         // 128
    if (m == 0 && tid == 0) g_flag = 0;
    const float4* p4 = reinterpret_cast<const float4*>(w + (size_t)m * DIMV);
    uint32_t* out = reinterpret_cast<uint32_t*>(g_wq8 + (size_t)m * DIMV);
    float s = 0.0f;
    #pragma unroll
    for (int i = tid; i < DIMV / 4; i += 128) {
        float4 v = p4[i];
        s += v.x * v.x + v.y * v.y + v.z * v.z + v.w * v.w;
        out[i] = pack_e4m3x4(v);
    }
    #pragma unroll
    for (int o = 16; o; o >>= 1) s += __shfl_xor_sync(0xFFFFFFFFu, s, o);
    __shared__ float ws[4];
    if ((tid & 31) == 0) ws[tid >> 5] = s;
    __syncthreads();
    if (tid == 0) g_wnorm[m] = ws[0] + ws[1] + ws[2] + ws[3];
}

// ---------------- kernel 2: prep — X -> e4m3, fused xd, zero out ------------
__global__ void __launch_bounds__(256)
prep_kernel(const float* __restrict__ Q, const float* __restrict__ Kin,
            const float* __restrict__ mask, float* __restrict__ out) {
    int warp = threadIdx.x >> 5;
    int lane = threadIdx.x & 31;
    int grow = blockIdx.x * 8 + warp;          // 0..NROWS-1
    const float* src;
    float ms;
    if (grow < RROWS) { src = Q + (size_t)grow * DIMV; ms = 1.0f; }
    else { int kr = grow - RROWS; src = Kin + (size_t)kr * DIMV; ms = mask[kr]; }

    const float4* s4 = reinterpret_cast<const float4*>(src);
    uint32_t* o4 = reinterpret_cast<uint32_t*>(g_xq8 + (size_t)grow * DIMV);
    float s = 0.0f;
    #pragma unroll
    for (int j = 0; j < 8; j++) {
        float4 v = s4[lane + 32 * j];
        v.x *= ms; v.y *= ms; v.z *= ms; v.w *= ms;
        s += v.x * v.x + v.y * v.y + v.z * v.z + v.w * v.w;
        o4[lane + 32 * j] = pack_e4m3x4(v);
    }
    #pragma unroll
    for (int o = 16; o; o >>= 1) s += __shfl_xor_sync(0xFFFFFFFFu, s, o);
    if (lane == 0) g_xd[grow] = 0.5f * s;

    // unconditional zero of the output slice (fallback overwrites if flagged)
    float4* oz = reinterpret_cast<float4*>(out) + (size_t)blockIdx.x * 1024;
    #pragma unroll
    for (int j = 0; j < 4; j++)
        oz[threadIdx.x + 256 * j] = make_float4(0.f, 0.f, 0.f, 0.f);
}

// ---------------- kernel 3: fp8 certificate GEMM ----------------------------
#define CT_STAGE_BYTES 16384            // A 8KB + B 8KB
#define CT_DYN (4 * CT_STAGE_BYTES)     // 64 KB

extern __shared__ __align__(128) unsigned char ct_sm[];

__global__ void __launch_bounds__(256, 2)
cert_gemm() {
    const int tid  = threadIdx.x;
    const int lane = tid & 31;
    const int warp = tid >> 5;
    const int wm = warp >> 1;
    const int wn = warp & 1;
    const int blockRow = blockIdx.y * 128;
    const int bn = blockIdx.x * 128;

    const uint32_t smb = smem_u32(ct_sm);

    const int lrow = tid >> 2;           // 0..63
    const int lchunk = tid & 3;
    int offA[2], offB[2];
    const unsigned char* srcA[2];
    const unsigned char* srcB[2];
    #pragma unroll
    for (int h = 0; h < 2; h++) {
        int r = lrow + h * 64;
        offA[h] = swz(r, lchunk);
        offB[h] = swz(r, lchunk);
        srcA[h] = g_xq8 + (size_t)(blockRow + r) * DIMV + lchunk * 16;
        srcB[h] = g_wq8 + (size_t)(bn + r) * DIMV + lchunk * 16;
    }

    int lA[2][2], lB[4][2];
    #pragma unroll
    for (int kh = 0; kh < 2; kh++) {
        #pragma unroll
        for (int mi = 0; mi < 2; mi++)
            lA[mi][kh] = swz(wm * 32 + mi * 16 + (lane & 15), kh * 2 + (lane >> 4));
        #pragma unroll
        for (int i = 0; i < 4; i++)
            lB[i][kh] = swz(wn * 64 + i * 16 + (lane & 7) + ((lane >> 4) << 3),
                            kh * 2 + ((lane >> 3) & 1));
    }

    float acc[2][8][4];
    #pragma unroll
    for (int mi = 0; mi < 2; mi++)
        #pragma unroll
        for (int nj = 0; nj < 8; nj++)
            #pragma unroll
            for (int e = 0; e < 4; e++) acc[mi][nj][e] = 0.0f;

    #pragma unroll
    for (int kt = 0; kt < 3; kt++) {
        uint32_t ab = smb + (kt & 3) * CT_STAGE_BYTES;
        uint32_t bb = ab + 8192;
        #pragma unroll
        for (int h = 0; h < 2; h++) {
            cp16(ab + offA[h], srcA[h] + kt * 64);
            cp16(bb + offB[h], srcB[h] + kt * 64);
        }
        CP_COMMIT();
    }

    const int NKT = DIMV / 64;           // 16 stages
    for (int kt = 0; kt < NKT; kt++) {
        CP_WAIT2();
        __syncthreads();
        if (kt + 3 < NKT) {
            int nk = kt + 3;
            uint32_t ab = smb + (nk & 3) * CT_STAGE_BYTES;
            uint32_t bb = ab + 8192;
            #pragma unroll
            for (int h = 0; h < 2; h++) {
                cp16(ab + offA[h], srcA[h] + nk * 64);
                cp16(bb + offB[h], srcB[h] + nk * 64);
            }
        }
        CP_COMMIT();

        uint32_t ab = smb + (kt & 3) * CT_STAGE_BYTES;
        uint32_t bb = ab + 8192;
        #pragma unroll
        for (int kh = 0; kh < 2; kh++) {
            uint32_t a0[4], a1[4], b[4][4];
            ldmx4(a0, ab + lA[0][kh]);
            ldmx4(a1, ab + lA[1][kh]);
            #pragma unroll
            for (int i = 0; i < 4; i++) ldmx4(b[i], bb + lB[i][kh]);
            #pragma unroll
            for (int i = 0; i < 4; i++) {
                mma_fp8(acc[0][2 * i],     a0, b[i][0], b[i][1]);
                mma_fp8(acc[0][2 * i + 1], a0, b[i][2], b[i][3]);
                mma_fp8(acc[1][2 * i],     a1, b[i][0], b[i][1]);
                mma_fp8(acc[1][2 * i + 1], a1, b[i][2], b[i][3]);
            }
        }
        __syncthreads();
    }

    // ---- epilogue: rigor guards + per-row fp8 threshold ----
    bool bad = false;
    if (!(g_wnorm[tid] <= 1250.0f)) bad = true;
    if (!(g_wnorm[tid + 256] <= 1250.0f)) bad = true;
    #pragma unroll
    for (int mi = 0; mi < 2; mi++) {
        int r0 = blockRow + wm * 32 + mi * 16 + (lane >> 2);
        float xd0 = g_xd[r0];
        float xd1 = g_xd[r0 + 8];
        if (!(xd0 <= 7000.0f) || !(xd1 <= 7000.0f)) bad = true;   // catches NaN
        float t0 = xd0 - 118.0f - 6.5f * sqrtf(fmaxf(xd0, 0.0f));
        float t1 = xd1 - 118.0f - 6.5f * sqrtf(fmaxf(xd1, 0.0f));
        #pragma unroll
        for (int nj = 0; nj < 8; nj++) {
            if (!(acc[mi][nj][0] <= t0)) bad = true;
            if (!(acc[mi][nj][1] <= t0)) bad = true;
            if (!(acc[mi][nj][2] <= t1)) bad = true;
            if (!(acc[mi][nj][3] <= t1)) bad = true;
        }
    }
    if (__syncthreads_or(bad ? 1 : 0)) {
        if (tid == 0) atomicOr(&g_flag, 1);
    }
}

// ================= gated exact fp32 fallback (grid-stride, runs iff g_flag) =
#define BMt 128
#define BNt 64
#define BKt 16
#define FEAT_TILES ((MFEAT / BNt) * (NROWS / BMt))   // 8 * 256 = 2048
__global__ void __launch_bounds__(256)
feat_gemm(const float* __restrict__ Q, const float* __restrict__ Kin,
          const float* __restrict__ mask, const float* __restrict__ w) {
    if (g_flag == 0) return;
    __shared__ float As[2][BKt][BMt];
    __shared__ float Bs[2][BKt][BNt];

    const int tid = threadIdx.x;
    const int tx = tid & 15;
    const int ty = tid >> 4;
    const int lrow = tid >> 2;
    const int lk   = (tid & 3) * 4;
    const int qsw  = (tid & 3);

    for (int tile = blockIdx.x; tile < FEAT_TILES; tile += gridDim.x) {
        const int bm = (tile >> 3) * BMt;          // 256 M-tiles
        const int bn = (tile & 7) * BNt;           // 8 N-tiles

        const float* aptr[2];
        float ascale[2];
        #pragma unroll
        for (int i = 0; i < 2; i++) {
            int gr = bm + lrow + 64 * i;
            if (gr < RROWS) { aptr[i] = Q + (size_t)gr * DIMV; ascale[i] = 1.0f; }
            else { int kr = gr - RROWS; aptr[i] = Kin + (size_t)kr * DIMV; ascale[i] = mask[kr]; }
        }
        const float* bptr = w + (size_t)(bn + lrow) * DIMV;

        float4 aReg[2], bReg;
        float acc[8][4];
        #pragma unroll
        for (int i = 0; i < 8; i++)
            #pragma unroll
            for (int j = 0; j < 4; j++) acc[i][j] = 0.0f;

        #pragma unroll
        for (int i = 0; i < 2; i++) {
            float4 v = *reinterpret_cast<const float4*>(aptr[i] + lk);
            v.x *= ascale[i]; v.y *= ascale[i]; v.z *= ascale[i]; v.w *= ascale[i];
            aReg[i] = v;
        }
        bReg = *reinterpret_cast<const float4*>(bptr + lk);
        {
            #pragma unroll
            for (int i = 0; i < 2; i++) {
                int row = lrow + 64 * i;
                int col = row ^ (qsw * 8);
                As[0][lk + 0][col] = aReg[i].x;
                As[0][lk + 1][col] = aReg[i].y;
                As[0][lk + 2][col] = aReg[i].z;
                As[0][lk + 3][col] = aReg[i].w;
            }
            int col = lrow ^ (qsw * 8);
            Bs[0][lk + 0][col] = bReg.x;
            Bs[0][lk + 1][col] = bReg.y;
            Bs[0][lk + 2][col] = bReg.z;
            Bs[0][lk + 3][col] = bReg.w;
        }
        __syncthreads();

        int buf = 0;
        const int NKT = DIMV / BKt;
        for (int kt = 0; kt < NKT; kt++) {
            if (kt < NKT - 1) {
                int k0 = (kt + 1) * BKt;
                #pragma unroll
                for (int i = 0; i < 2; i++) {
                    float4 v = *reinterpret_cast<const float4*>(aptr[i] + k0 + lk);
                    v.x *= ascale[i]; v.y *= ascale[i]; v.z *= ascale[i]; v.w *= ascale[i];
                    aReg[i] = v;
                }
                bReg = *reinterpret_cast<const float4*>(bptr + k0 + lk);
            }
            #pragma unroll
            for (int k = 0; k < BKt; k++) {
                int qr = k >> 2;
                int cA = (ty ^ qr) * 8;
                float4 a0 = *reinterpret_cast<const float4*>(&As[buf][k][cA]);
                float4 a1 = *reinterpret_cast<const float4*>(&As[buf][k][cA + 4]);
                int cB = (tx * 4) ^ (qr * 8);
                float4 b0 = *reinterpret_cast<const float4*>(&Bs[buf][k][cB]);
                float av[8] = {a0.x, a0.y, a0.z, a0.w, a1.x, a1.y, a1.z, a1.w};
                float bv[4] = {b0.x, b0.y, b0.z, b0.w};
                #pragma unroll
                for (int i = 0; i < 8; i++)
                    #pragma unroll
                    for (int j = 0; j < 4; j++)
                        acc[i][j] = fmaf(av[i], bv[j], acc[i][j]);
            }
            if (kt < NKT - 1) {
                int nb = buf ^ 1;
                #pragma unroll
                for (int i = 0; i < 2; i++) {
                    int row = lrow + 64 * i;
                    int col = row ^ (qsw * 8);
                    As[nb][lk + 0][col] = aReg[i].x;
                    As[nb][lk + 1][col] = aReg[i].y;
                    As[nb][lk + 2][col] = aReg[i].z;
                    As[nb][lk + 3][col] = aReg[i].w;
                }
                int col = lrow ^ (qsw * 8);
                Bs[nb][lk + 0][col] = bReg.x;
                Bs[nb][lk + 1][col] = bReg.y;
                Bs[nb][lk + 2][col] = bReg.z;
                Bs[nb][lk + 3][col] = bReg.w;
                __syncthreads();
                buf = nb;
            }
        }
        #pragma unroll
        for (int i = 0; i < 8; i++) {
            int r = bm + ty * 8 + i;
            float xd = g_xd[r];
            float4 o;
            o.x = expf(acc[i][0] - xd) * RSQRTM;
            o.y = expf(acc[i][1] - xd) * RSQRTM;
            o.z = expf(acc[i][2] - xd) * RSQRTM;
            o.w = expf(acc[i][3] - xd) * RSQRTM;
            float* outp = (r < RROWS) ? (g_qp + (size_t)r * MFEAT)
                                      : (g_kp + (size_t)(r - RROWS) * MFEAT);
            *reinterpret_cast<float4*>(outp + bn + tx * 4) = o;
        }
        __syncthreads();
    }
}

// ksum then D (small, grid-stride)
__global__ void ksum_kernel() {
    if (g_flag == 0) return;
    int idx = blockIdx.x * 256 + threadIdx.x;    // grid 8 blocks
    if (idx >= BB * MFEAT) return;
    int b = idx / MFEAT, m = idx % MFEAT;
    float acc = 0.0f;
    for (int t = 0; t < TT; t++)
        acc += g_kp[((size_t)b * TT + t) * MFEAT + m];
    g_ksum[idx] = acc;
}

__global__ void dvec_kernel() {
    if (g_flag == 0) return;
    for (int bt = blockIdx.x; bt < BB * TT; bt += gridDim.x) {   // grid 1024
        int b = bt / TT;
        int tid = threadIdx.x;
        float acc = 0.0f;
        #pragma unroll
        for (int m = tid; m < MFEAT; m += 128)
            acc += g_qp[(size_t)bt * MFEAT + m] * g_ksum[b * MFEAT + m];
        #pragma unroll
        for (int o = 16; o; o >>= 1) acc += __shfl_xor_sync(0xFFFFFFFFu, acc, o);
        __shared__ float ws[4];
        if ((tid & 31) == 0) ws[tid >> 5] = acc;
        __syncthreads();
        if (tid == 0) g_D[bt] = ws[0] + ws[1] + ws[2] + ws[3];
        __syncthreads();
    }
}

#define KPTV_TILES ((MFEAT / 16) * (DIMV / 16) * BB)   // 8192
__global__ void kptv_kernel(const float* __restrict__ V,
                            const float* __restrict__ mask) {
    if (g_flag == 0) return;
    __shared__ float Vs[16][17], Ks[16][17];
    int tx = threadIdx.x, ty = threadIdx.y;
    for (int tile = blockIdx.x; tile < KPTV_TILES; tile += gridDim.x) {  // grid 512
        int b = tile / ((MFEAT / 16) * (DIMV / 16));
        int rem = tile % ((MFEAT / 16) * (DIMV / 16));
        int n0 = (rem / (MFEAT / 16)) * 16;
        int m0 = (rem % (MFEAT / 16)) * 16;
        float acc = 0.0f;
        for (int t0 = 0; t0 < TT; t0 += 16) {
            int t = t0 + ty;
            Vs[ty][tx] = V[((size_t)b * TT + t) * DIMV + n0 + tx] * mask[b * TT + t];
            Ks[ty][tx] = g_kp[((size_t)b * TT + t) * MFEAT + m0 + tx];
            __syncthreads();
            #pragma unroll
            for (int kk = 0; kk < 16; kk++)
                acc = fmaf(Vs[kk][ty], Ks[kk][tx], acc);
            __syncthreads();
        }
        g_kptv[((size_t)b * DIMV + n0 + ty) * MFEAT + m0 + tx] = acc;
        __syncthreads();
    }
}

#define YF_TILES ((DIMV / 16) * (TT / 16) * BB)        // 65536
__global__ void y_full_kernel(float* __restrict__ out) {
    if (g_flag == 0) return;
    __shared__ float Qs[16][17], Ps[16][17];
    int tx = threadIdx.x, ty = threadIdx.y;
    for (int tile = blockIdx.x; tile < YF_TILES; tile += gridDim.x) {   // grid 1024
        int b = tile / ((DIMV / 16) * (TT / 16));
        int rem = tile % ((DIMV / 16) * (TT / 16));
        int t0 = (rem / (DIMV / 16)) * 16;
        int n0 = (rem % (DIMV / 16)) * 16;
        float acc = 0.0f;
        for (int m0 = 0; m0 < MFEAT; m0 += 16) {
            Qs[ty][tx] = g_qp[((size_t)b * TT + t0 + ty) * MFEAT + m0 + tx];
            Ps[ty][tx] = g_kptv[((size_t)b * DIMV + n0 + ty) * MFEAT + m0 + tx];
            __syncthreads();
            #pragma unroll
            for (int kk = 0; kk < 16; kk++)
                acc = fmaf(Qs[ty][kk], Ps[tx][kk], acc);
            __syncthreads();
        }
        int t = t0 + ty;
        float inv = 1.0f / (g_D[b * TT + t] + EPSV);
        out[((size_t)b * TT + t) * DIMV + n0 + tx] = acc * inv * inv;
        __syncthreads();
    }
}

// ---------------- launch ----------------
extern "C" void kernel_launch(void* const* d_in, const int* in_sizes, int n_in,
                              void* d_out, int out_size) {
    const float* Q    = (const float*)d_in[0];
    const float* K    = (const float*)d_in[1];
    const float* V    = (const float*)d_in[2];
    const float* mask = (const float*)d_in[3];
    const float* w    = (const float*)d_in[4];
    float* out = (float*)d_out;
    (void)in_sizes; (void)n_in; (void)out_size;

    cudaFuncSetAttribute(cert_gemm, cudaFuncAttributeMaxDynamicSharedMemorySize, CT_DYN);

    wconv_kernel<<<MFEAT, 128>>>(w);
    prep_kernel<<<NROWS / 8, 256>>>(Q, K, mask, out);
    cert_gemm<<<dim3(MFEAT / 128, NROWS / 128), 256, CT_DYN>>>();

    // gated exact fallback (fast no-ops when certificate passed)
    feat_gemm<<<512, 256>>>(Q, K, mask, w);
    ksum_kernel<<<8, 256>>>();
    dvec_kernel<<<1024, 128>>>();
    kptv_kernel<<<512, dim3(16, 16)>>>(V, mask);
    y_full_kernel<<<1024, dim3(16, 16)>>>(out);
}